// round 6
// baseline (speedup 1.0000x reference)
#include <cuda_runtime.h>

#define EPSV  1e-8f
#define SLOPE 0.01f
#define HID   32

// lrelu(x) == fmaxf(x, SLOPE*x) exactly, since SLOPE < 1 (FMUL+FMNMX, no predication)
__device__ __forceinline__ float lrelu(float x) { return fmaxf(x, SLOPE * x); }

__global__ __launch_bounds__(128)
void aero_kernel(const float* __restrict__ v, const float* __restrict__ w,
                 const float* __restrict__ W1, const float* __restrict__ b1,
                 const float* __restrict__ W2, const float* __restrict__ b2,
                 const float* __restrict__ Wd1, const float* __restrict__ bd1,
                 const float* __restrict__ Wd2, const float* __restrict__ bd2,
                 const float* __restrict__ bias,
                 float* __restrict__ out, int n)
{
    // Weights staged per CTA; 32x32 matrices transposed so inner-j reads are
    // contiguous (LDS.128 broadcast).
    __shared__ float sW1[HID * 3], sb1[HID];
    __shared__ float sW2t[HID * HID], sb2[HID];
    __shared__ float sWd1t[HID * HID], sbd1[HID];
    __shared__ float sWd2[3 * HID], sbd2[3], sbias[3];

    const int tid = threadIdx.x;
    for (int i = tid; i < HID * 3; i += blockDim.x) sW1[i] = W1[i];
    for (int i = tid; i < HID; i += blockDim.x) {
        sb1[i] = b1[i]; sb2[i] = b2[i]; sbd1[i] = bd1[i];
    }
    for (int i = tid; i < HID * HID; i += blockDim.x) {
        int j = i / HID, k = i % HID;
        sW2t[k * HID + j]  = W2[i];
        sWd1t[k * HID + j] = Wd1[i];
    }
    for (int i = tid; i < 3 * HID; i += blockDim.x) sWd2[i] = Wd2[i];
    if (tid < 3) { sbd2[tid] = bd2[tid]; sbias[tid] = bias[tid]; }
    __syncthreads();

    const int gid = blockIdx.x * blockDim.x + tid;
    const int i0  = 2 * gid;               // first element of this thread's pair
    if (i0 >= n) return;
    const bool have2 = (i0 + 1) < n;

    // ---- load inputs (6 contiguous floats per tensor per pair, 8B-aligned) ----
    float vx[2], vy[2], vz[2], wx[2], wy[2], wz[2];
    {
        const float2* v2 = reinterpret_cast<const float2*>(v) + 3 * gid;
        const float2* w2 = reinterpret_cast<const float2*>(w) + 3 * gid;
        float2 a = v2[0];
        float2 bq = have2 ? v2[1] : make_float2(0.f, 0.f);
        float2 c = have2 ? v2[2] : make_float2(0.f, 0.f);
        vx[0] = a.x; vy[0] = a.y; vz[0] = bq.x;
        vx[1] = bq.y; vy[1] = c.x; vz[1] = c.y;
        a = w2[0];
        bq = have2 ? w2[1] : make_float2(0.f, 0.f);
        c = have2 ? w2[2] : make_float2(0.f, 0.f);
        wx[0] = a.x; wy[0] = a.y; wz[0] = bq.x;
        wx[1] = bq.y; wy[1] = c.x; wz[1] = c.y;
    }

    // ---- Gram-Schmidt frame per element (closed form) ----
    float v0[2], v1[2], v2e[2], w0[2], w1[2], w2e[2], u0[2], u1[2], u2[2];
    float f0[2], f1[2], f2[2];
    #pragma unroll
    for (int e = 0; e < 2; e++) {
        const float nv = sqrtf(fmaf(vx[e], vx[e], fmaf(vy[e], vy[e], vz[e] * vz[e])));
        const float iv = 1.0f / (nv + EPSV);
        v0[e] = vx[e] * iv; v1[e] = vy[e] * iv; v2e[e] = vz[e] * iv;
        const float d = fmaf(wx[e], v0[e], fmaf(wy[e], v1[e], wz[e] * v2e[e]));
        const float ox = fmaf(-d, v0[e], wx[e]);
        const float oy = fmaf(-d, v1[e], wy[e]);
        const float oz = fmaf(-d, v2e[e], wz[e]);
        const float nw = sqrtf(fmaf(ox, ox, fmaf(oy, oy, oz * oz)));
        const float iw = 1.0f / (nw + EPSV);
        w0[e] = ox * iw; w1[e] = oy * iw; w2e[e] = oz * iw;
        u0[e] = fmaf(v1[e], w2e[e], -v2e[e] * w1[e]);
        u1[e] = fmaf(v2e[e], w0[e], -v0[e] * w2e[e]);
        u2[e] = fmaf(v0[e], w1[e], -v1[e] * w0[e]);
        f0[e] = fmaf(vx[e], v0[e], fmaf(vy[e], v1[e], vz[e] * v2e[e]));
        f1[e] = d;
        f2[e] = fmaf(wx[e], w0[e], fmaf(wy[e], w1[e], wz[e] * w2e[e]));
    }

    // ---- Layer 1 ----
    float h1[2][HID];
    #pragma unroll
    for (int j = 0; j < HID; j++) {
        const float a0 = sW1[j * 3 + 0], a1 = sW1[j * 3 + 1], a2 = sW1[j * 3 + 2];
        const float bb = sb1[j];
        #pragma unroll
        for (int e = 0; e < 2; e++)
            h1[e][j] = lrelu(fmaf(f0[e], a0, fmaf(f1[e], a1, fmaf(f2[e], a2, bb))));
    }

    // ---- Layer 2: h = lrelu(h1 @ W2^T + b2) * h1 ----
    float acc[2][HID];
    #pragma unroll
    for (int j = 0; j < HID; j++) { const float bb = sb2[j]; acc[0][j] = bb; acc[1][j] = bb; }
    #pragma unroll
    for (int k = 0; k < HID; k++) {
        const float a0 = h1[0][k], a1 = h1[1][k];
        const float4* wr = reinterpret_cast<const float4*>(&sW2t[k * HID]);
        #pragma unroll
        for (int j4 = 0; j4 < HID / 4; j4++) {
            const float4 wv = wr[j4];
            acc[0][j4*4+0] = fmaf(a0, wv.x, acc[0][j4*4+0]);
            acc[0][j4*4+1] = fmaf(a0, wv.y, acc[0][j4*4+1]);
            acc[0][j4*4+2] = fmaf(a0, wv.z, acc[0][j4*4+2]);
            acc[0][j4*4+3] = fmaf(a0, wv.w, acc[0][j4*4+3]);
            acc[1][j4*4+0] = fmaf(a1, wv.x, acc[1][j4*4+0]);
            acc[1][j4*4+1] = fmaf(a1, wv.y, acc[1][j4*4+1]);
            acc[1][j4*4+2] = fmaf(a1, wv.z, acc[1][j4*4+2]);
            acc[1][j4*4+3] = fmaf(a1, wv.w, acc[1][j4*4+3]);
        }
    }
    #pragma unroll
    for (int j = 0; j < HID; j++) {
        h1[0][j] = lrelu(acc[0][j]) * h1[0][j];
        h1[1][j] = lrelu(acc[1][j]) * h1[1][j];
    }

    // ---- Layer 3: g = lrelu(h @ Wd1^T + bd1) ----
    #pragma unroll
    for (int j = 0; j < HID; j++) { const float bb = sbd1[j]; acc[0][j] = bb; acc[1][j] = bb; }
    #pragma unroll
    for (int k = 0; k < HID; k++) {
        const float a0 = h1[0][k], a1 = h1[1][k];
        const float4* wr = reinterpret_cast<const float4*>(&sWd1t[k * HID]);
        #pragma unroll
        for (int j4 = 0; j4 < HID / 4; j4++) {
            const float4 wv = wr[j4];
            acc[0][j4*4+0] = fmaf(a0, wv.x, acc[0][j4*4+0]);
            acc[0][j4*4+1] = fmaf(a0, wv.y, acc[0][j4*4+1]);
            acc[0][j4*4+2] = fmaf(a0, wv.z, acc[0][j4*4+2]);
            acc[0][j4*4+3] = fmaf(a0, wv.w, acc[0][j4*4+3]);
            acc[1][j4*4+0] = fmaf(a1, wv.x, acc[1][j4*4+0]);
            acc[1][j4*4+1] = fmaf(a1, wv.y, acc[1][j4*4+1]);
            acc[1][j4*4+2] = fmaf(a1, wv.z, acc[1][j4*4+2]);
            acc[1][j4*4+3] = fmaf(a1, wv.w, acc[1][j4*4+3]);
        }
    }

    // ---- Layer 4 + rotation + bias ----
    float y0[2], y1[2], y2[2];
    #pragma unroll
    for (int e = 0; e < 2; e++) { y0[e] = sbd2[0]; y1[e] = sbd2[1]; y2[e] = sbd2[2]; }
    #pragma unroll
    for (int k = 0; k < HID; k++) {
        const float wd0 = sWd2[0 * HID + k], wd1 = sWd2[1 * HID + k], wd2v = sWd2[2 * HID + k];
        #pragma unroll
        for (int e = 0; e < 2; e++) {
            const float g = lrelu(acc[e][k]);
            y0[e] = fmaf(g, wd0, y0[e]);
            y1[e] = fmaf(g, wd1, y1[e]);
            y2[e] = fmaf(g, wd2v, y2[e]);
        }
    }

    float o[6];
    #pragma unroll
    for (int e = 0; e < 2; e++) {
        o[e*3+0] = fmaf(v0[e], y0[e], fmaf(w0[e], y1[e], fmaf(u0[e], y2[e], sbias[0])));
        o[e*3+1] = fmaf(v1[e], y0[e], fmaf(w1[e], y1[e], fmaf(u1[e], y2[e], sbias[1])));
        o[e*3+2] = fmaf(v2e[e], y0[e], fmaf(w2e[e], y1[e], fmaf(u2[e], y2[e], sbias[2])));
    }

    float2* o2 = reinterpret_cast<float2*>(out) + 3 * gid;
    o2[0] = make_float2(o[0], o[1]);
    if (have2) {
        o2[1] = make_float2(o[2], o[3]);
        o2[2] = make_float2(o[4], o[5]);
    } else {
        out[i0 * 3 + 2] = o[2];
    }
}

extern "C" void kernel_launch(void* const* d_in, const int* in_sizes, int n_in,
                              void* d_out, int out_size)
{
    const float* v    = (const float*)d_in[0];
    const float* w    = (const float*)d_in[1];
    const float* W1   = (const float*)d_in[2];
    const float* b1   = (const float*)d_in[3];
    const float* W2   = (const float*)d_in[4];
    const float* b2   = (const float*)d_in[5];
    const float* Wd1  = (const float*)d_in[6];
    const float* bd1  = (const float*)d_in[7];
    const float* Wd2  = (const float*)d_in[8];
    const float* bd2  = (const float*)d_in[9];
    const float* bias = (const float*)d_in[10];
    float* out = (float*)d_out;

    const int n = in_sizes[0] / 3;
    const int threads = 128;
    const int pairs = (n + 1) / 2;
    const int blocks = (pairs + threads - 1) / threads;
    aero_kernel<<<blocks, threads>>>(v, w, W1, b1, W2, b2, Wd1, bd1,
                                     Wd2, bd2, bias, out, n);
}

// round 7
// speedup vs baseline: 2.4790x; 2.4790x over previous
#include <cuda_runtime.h>

#define EPSV  1e-8f
#define SLOPE 0.01f
#define HID   32

// ---- constant-memory weight store (filled via async D2D memcpy each launch) ----
__constant__ float              cW1[HID * 3];      // [j][3] row-major
__constant__ float              cb1[HID];
__constant__ ulonglong2         cW2[HID * 8];      // W2  [j][k] row-major, 4 floats per ull2
__constant__ float              cb2[HID];
__constant__ ulonglong2         cWd1[HID * 8];     // Wd1 [j][k] row-major
__constant__ float              cbd1[HID];
__constant__ ulonglong2         cWd2[3 * 8];       // Wd2 [3][32] row-major
__constant__ float              cbd2[3];
__constant__ float              cbias[3];

// lrelu(x) == fmaxf(x, SLOPE*x) exactly, since SLOPE < 1
__device__ __forceinline__ float lrelu(float x) { return fmaxf(x, SLOPE * x); }

__device__ __forceinline__ unsigned long long pack2(float x, float y) {
    unsigned long long r;
    asm("mov.b64 %0, {%1, %2};" : "=l"(r) : "f"(x), "f"(y));
    return r;
}
__device__ __forceinline__ unsigned long long fma2(unsigned long long a,
                                                   unsigned long long b,
                                                   unsigned long long c) {
    unsigned long long d;
    asm("fma.rn.f32x2 %0, %1, %2, %3;" : "=l"(d) : "l"(a), "l"(b), "l"(c));
    return d;
}
__device__ __forceinline__ float hadd2(unsigned long long a) {
    float x, y;
    asm("mov.b64 {%0, %1}, %2;" : "=f"(x), "=f"(y) : "l"(a));
    return x + y;
}

__global__ __launch_bounds__(256)
void aero_kernel(const float* __restrict__ v, const float* __restrict__ w,
                 float* __restrict__ out, int n)
{
    const int idx = blockIdx.x * blockDim.x + threadIdx.x;
    if (idx >= n) return;

    const float vx = v[idx * 3 + 0], vy = v[idx * 3 + 1], vz = v[idx * 3 + 2];
    const float wx = w[idx * 3 + 0], wy = w[idx * 3 + 1], wz = w[idx * 3 + 2];

    // ---- Gram-Schmidt (closed form, matches reference arithmetic) ----
    const float nv = sqrtf(fmaf(vx, vx, fmaf(vy, vy, vz * vz)));
    const float iv = 1.0f / (nv + EPSV);
    const float v0 = vx * iv, v1 = vy * iv, v2 = vz * iv;
    const float d  = fmaf(wx, v0, fmaf(wy, v1, wz * v2));
    const float ox = fmaf(-d, v0, wx);
    const float oy = fmaf(-d, v1, wy);
    const float oz = fmaf(-d, v2, wz);
    const float nw = sqrtf(fmaf(ox, ox, fmaf(oy, oy, oz * oz)));
    const float iw = 1.0f / (nw + EPSV);
    const float w0 = ox * iw, w1 = oy * iw, w2 = oz * iw;
    const float u0 = fmaf(v1, w2, -v2 * w1);
    const float u1 = fmaf(v2, w0, -v0 * w2);
    const float u2 = fmaf(v0, w1, -v1 * w0);
    const float f0 = fmaf(vx, v0, fmaf(vy, v1, vz * v2));
    const float f1 = d;
    const float f2 = fmaf(wx, w0, fmaf(wy, w1, wz * w2));

    // ---- Layer 1: h1 = lrelu(feat @ W1^T + b1)  (scalar, constants via LDCU) ----
    float h1[HID];
    #pragma unroll
    for (int j = 0; j < HID; j++) {
        h1[j] = lrelu(fmaf(f0, cW1[j * 3 + 0],
                      fmaf(f1, cW1[j * 3 + 1],
                      fmaf(f2, cW1[j * 3 + 2], cb1[j]))));
    }

    // pack activation k-pairs once
    unsigned long long hp[HID / 2];
    #pragma unroll
    for (int t = 0; t < HID / 2; t++) hp[t] = pack2(h1[2 * t], h1[2 * t + 1]);

    // ---- Layer 2: h = lrelu(h1 @ W2^T + b2) * h1   (f32x2 over k-pairs) ----
    #pragma unroll
    for (int j = 0; j < HID; j++) {
        unsigned long long acc = 0ull;   // {0.0f, 0.0f}
        #pragma unroll
        for (int t = 0; t < 8; t++) {
            const ulonglong2 q = cW2[j * 8 + t];   // 4 weights: k=4t..4t+3
            acc = fma2(hp[2 * t + 0], q.x, acc);
            acc = fma2(hp[2 * t + 1], q.y, acc);
        }
        h1[j] = lrelu(hadd2(acc) + cb2[j]) * h1[j];
    }
    #pragma unroll
    for (int t = 0; t < HID / 2; t++) hp[t] = pack2(h1[2 * t], h1[2 * t + 1]);

    // ---- Layer 3: g = lrelu(h @ Wd1^T + bd1) ----
    float g[HID];
    #pragma unroll
    for (int j = 0; j < HID; j++) {
        unsigned long long acc = 0ull;
        #pragma unroll
        for (int t = 0; t < 8; t++) {
            const ulonglong2 q = cWd1[j * 8 + t];
            acc = fma2(hp[2 * t + 0], q.x, acc);
            acc = fma2(hp[2 * t + 1], q.y, acc);
        }
        g[j] = lrelu(hadd2(acc) + cbd1[j]);
    }
    #pragma unroll
    for (int t = 0; t < HID / 2; t++) hp[t] = pack2(g[2 * t], g[2 * t + 1]);

    // ---- Layer 4: y = g @ Wd2^T + bd2  (3 outputs, packed) ----
    float y[3];
    #pragma unroll
    for (int r = 0; r < 3; r++) {
        unsigned long long acc = 0ull;
        #pragma unroll
        for (int t = 0; t < 8; t++) {
            const ulonglong2 q = cWd2[r * 8 + t];
            acc = fma2(hp[2 * t + 0], q.x, acc);
            acc = fma2(hp[2 * t + 1], q.y, acc);
        }
        y[r] = hadd2(acc) + cbd2[r];
    }

    // ---- out = R @ y + bias, R columns = (v_on, w_on, u_on) ----
    out[idx * 3 + 0] = fmaf(v0, y[0], fmaf(w0, y[1], fmaf(u0, y[2], cbias[0])));
    out[idx * 3 + 1] = fmaf(v1, y[0], fmaf(w1, y[1], fmaf(u1, y[2], cbias[1])));
    out[idx * 3 + 2] = fmaf(v2, y[0], fmaf(w2, y[1], fmaf(u2, y[2], cbias[2])));
}

extern "C" void kernel_launch(void* const* d_in, const int* in_sizes, int n_in,
                              void* d_out, int out_size)
{
    const float* v = (const float*)d_in[0];
    const float* w = (const float*)d_in[1];

    // Stage weights into __constant__ (async D2D memcpy nodes; graph-capturable)
    cudaMemcpyToSymbolAsync(cW1,  d_in[2],  HID * 3 * sizeof(float), 0, cudaMemcpyDeviceToDevice, 0);
    cudaMemcpyToSymbolAsync(cb1,  d_in[3],  HID * sizeof(float),     0, cudaMemcpyDeviceToDevice, 0);
    cudaMemcpyToSymbolAsync(cW2,  d_in[4],  HID * HID * sizeof(float), 0, cudaMemcpyDeviceToDevice, 0);
    cudaMemcpyToSymbolAsync(cb2,  d_in[5],  HID * sizeof(float),     0, cudaMemcpyDeviceToDevice, 0);
    cudaMemcpyToSymbolAsync(cWd1, d_in[6],  HID * HID * sizeof(float), 0, cudaMemcpyDeviceToDevice, 0);
    cudaMemcpyToSymbolAsync(cbd1, d_in[7],  HID * sizeof(float),     0, cudaMemcpyDeviceToDevice, 0);
    cudaMemcpyToSymbolAsync(cWd2, d_in[8],  3 * HID * sizeof(float), 0, cudaMemcpyDeviceToDevice, 0);
    cudaMemcpyToSymbolAsync(cbd2, d_in[9],  3 * sizeof(float),       0, cudaMemcpyDeviceToDevice, 0);
    cudaMemcpyToSymbolAsync(cbias, d_in[10], 3 * sizeof(float),      0, cudaMemcpyDeviceToDevice, 0);

    float* out = (float*)d_out;
    const int n = in_sizes[0] / 3;
    const int threads = 256;
    const int blocks = (n + threads - 1) / threads;
    aero_kernel<<<blocks, threads>>>(v, w, out, n);
}

// round 8
// speedup vs baseline: 4.4168x; 1.7817x over previous
#include <cuda_runtime.h>

#define EPSV  1e-8f
#define SLOPE 0.01f
#define HID   32
#define TILES_PER_WARP 8
#define WARPS_PER_CTA  8

__device__ __forceinline__ float lrelu(float x) { return fmaxf(x, SLOPE * x); }

// pack {lo=x, hi=y} as bf16x2 (first PTX source -> high half)
__device__ __forceinline__ unsigned cvt2(float lo, float hi) {
    unsigned r;
    asm("cvt.rn.bf16x2.f32 %0, %1, %2;" : "=r"(r) : "f"(hi), "f"(lo));
    return r;
}

__device__ __forceinline__ void mma_bf16(float c[4],
                                         unsigned a0, unsigned a1, unsigned a2, unsigned a3,
                                         unsigned b0, unsigned b1) {
    asm("mma.sync.aligned.m16n8k16.row.col.f32.bf16.bf16.f32 "
        "{%0,%1,%2,%3},{%4,%5,%6,%7},{%8,%9},{%0,%1,%2,%3};"
        : "+f"(c[0]), "+f"(c[1]), "+f"(c[2]), "+f"(c[3])
        : "r"(a0), "r"(a1), "r"(a2), "r"(a3), "r"(b0), "r"(b1));
}

__global__ __launch_bounds__(WARPS_PER_CTA * 32)
void aero_kernel(const float* __restrict__ v, const float* __restrict__ w,
                 const float* __restrict__ W1, const float* __restrict__ b1,
                 const float* __restrict__ W2, const float* __restrict__ b2,
                 const float* __restrict__ Wd1, const float* __restrict__ bd1,
                 const float* __restrict__ Wd2, const float* __restrict__ bd2,
                 const float* __restrict__ bias,
                 float* __restrict__ out, int n)
{
    __shared__ float sfeat[WARPS_PER_CTA][32][3];
    __shared__ float sy[WARPS_PER_CTA][32][3];

    const int lane = threadIdx.x & 31;
    const int warp = threadIdx.x >> 5;
    const long gwarp = (long)blockIdx.x * WARPS_PER_CTA + warp;

    const int jn = lane >> 2;        // n-index within an n8 tile (0..7)
    const int kk = (lane & 3) * 2;   // k-pair base within k16 step
    const int cc = (lane & 3) * 2;   // col-pair base of C fragment

    // ================= per-warp weight fragment build (once) =================
    // Layer 1: B[k][n] = W1[n][k], K padded 3->16. Only b0 (k<8) can be nonzero.
    unsigned B1[4];
    #pragma unroll
    for (int nt = 0; nt < 4; nt++) {
        const int j = 8 * nt + jn;
        const float x = (kk     < 3) ? W1[j * 3 + kk]     : 0.0f;
        const float y = (kk + 1 < 3) ? W1[j * 3 + kk + 1] : 0.0f;
        B1[nt] = cvt2(x, y);
    }
    // Layers 2/3: B[k][n] = W[n][k], 32x32
    unsigned B2[2][4][2], B3[2][4][2];
    #pragma unroll
    for (int ks = 0; ks < 2; ks++)
        #pragma unroll
        for (int nt = 0; nt < 4; nt++) {
            const int j = 8 * nt + jn;
            const int k0 = 16 * ks + kk;
            B2[ks][nt][0] = cvt2(W2[j * HID + k0],     W2[j * HID + k0 + 1]);
            B2[ks][nt][1] = cvt2(W2[j * HID + k0 + 8], W2[j * HID + k0 + 9]);
            B3[ks][nt][0] = cvt2(Wd1[j * HID + k0],     Wd1[j * HID + k0 + 1]);
            B3[ks][nt][1] = cvt2(Wd1[j * HID + k0 + 8], Wd1[j * HID + k0 + 9]);
        }
    // Layer 4: B[k][n] = Wd2[n][k], n padded 3->8
    unsigned B4[2][2];
    #pragma unroll
    for (int ks = 0; ks < 2; ks++) {
        const int k0 = 16 * ks + kk;
        const float x0 = (jn < 3) ? Wd2[jn * HID + k0]     : 0.0f;
        const float x1 = (jn < 3) ? Wd2[jn * HID + k0 + 1] : 0.0f;
        const float x2 = (jn < 3) ? Wd2[jn * HID + k0 + 8] : 0.0f;
        const float x3 = (jn < 3) ? Wd2[jn * HID + k0 + 9] : 0.0f;
        B4[ks][0] = cvt2(x0, x1);
        B4[ks][1] = cvt2(x2, x3);
    }
    // bias fragments (fp32, accumulate exactly via C init)
    float bia1[4][2], bia2[4][2], bia3[4][2];
    #pragma unroll
    for (int nt = 0; nt < 4; nt++) {
        bia1[nt][0] = b1[8 * nt + cc];  bia1[nt][1] = b1[8 * nt + cc + 1];
        bia2[nt][0] = b2[8 * nt + cc];  bia2[nt][1] = b2[8 * nt + cc + 1];
        bia3[nt][0] = bd1[8 * nt + cc]; bia3[nt][1] = bd1[8 * nt + cc + 1];
    }
    float bia4[2];
    bia4[0] = (cc     < 3) ? bd2[cc]     : 0.0f;
    bia4[1] = (cc + 1 < 3) ? bd2[cc + 1] : 0.0f;
    const float bs0 = bias[0], bs1 = bias[1], bs2 = bias[2];

    // ============================ main tile loop ============================
    for (int t = 0; t < TILES_PER_WARP; t++) {
        const long rowbase = (gwarp * TILES_PER_WARP + t) * 32;
        if (rowbase >= n) break;
        const long row = rowbase + lane;
        const bool ok = row < n;

        // ---- Gram-Schmidt for row = rowbase + lane (one row per lane) ----
        float vx = 0, vy = 0, vz = 0, wx = 0, wy = 0, wz = 0;
        if (ok) {
            vx = v[row * 3 + 0]; vy = v[row * 3 + 1]; vz = v[row * 3 + 2];
            wx = w[row * 3 + 0]; wy = w[row * 3 + 1]; wz = w[row * 3 + 2];
        }
        const float nv = sqrtf(fmaf(vx, vx, fmaf(vy, vy, vz * vz)));
        const float iv = 1.0f / (nv + EPSV);
        const float v0 = vx * iv, v1 = vy * iv, v2 = vz * iv;
        const float d  = fmaf(wx, v0, fmaf(wy, v1, wz * v2));
        const float ox = fmaf(-d, v0, wx);
        const float oy = fmaf(-d, v1, wy);
        const float oz = fmaf(-d, v2, wz);
        const float nw = sqrtf(fmaf(ox, ox, fmaf(oy, oy, oz * oz)));
        const float iw = 1.0f / (nw + EPSV);
        const float w0 = ox * iw, w1 = oy * iw, w2 = oz * iw;
        const float u0 = fmaf(v1, w2, -v2 * w1);
        const float u1 = fmaf(v2, w0, -v0 * w2);
        const float u2 = fmaf(v0, w1, -v1 * w0);

        sfeat[warp][lane][0] = fmaf(vx, v0, fmaf(vy, v1, vz * v2)); // f0
        sfeat[warp][lane][1] = d;                                   // f1
        sfeat[warp][lane][2] = fmaf(wx, w0, fmaf(wy, w1, wz * w2)); // f2
        __syncwarp();

        // ---- two 16-row MMA tiles ----
        #pragma unroll
        for (int mt = 0; mt < 2; mt++) {
            const int r1 = mt * 16 + (lane >> 2);
            const int r2 = r1 + 8;

            // Layer 1: A from feat (K=3 padded into one k16 step)
            unsigned a0 = 0, a1 = 0;
            if ((lane & 3) == 0) {
                a0 = cvt2(sfeat[warp][r1][0], sfeat[warp][r1][1]);
                a1 = cvt2(sfeat[warp][r2][0], sfeat[warp][r2][1]);
            } else if ((lane & 3) == 1) {
                a0 = cvt2(sfeat[warp][r1][2], 0.0f);
                a1 = cvt2(sfeat[warp][r2][2], 0.0f);
            }
            float C[4][4];
            #pragma unroll
            for (int nt = 0; nt < 4; nt++) {
                C[nt][0] = bia1[nt][0]; C[nt][1] = bia1[nt][1];
                C[nt][2] = bia1[nt][0]; C[nt][3] = bia1[nt][1];
                mma_bf16(C[nt], a0, a1, 0u, 0u, B1[nt], 0u);
            }
            float h1r[16];
            #pragma unroll
            for (int q = 0; q < 16; q++) h1r[q] = lrelu(C[q >> 2][q & 3]);

            unsigned A[2][4];
            #pragma unroll
            for (int ks = 0; ks < 2; ks++)
                #pragma unroll
                for (int q = 0; q < 4; q++)
                    A[ks][q] = cvt2(h1r[8 * ks + 2 * q], h1r[8 * ks + 2 * q + 1]);

            // Layer 2: h = lrelu(h1 @ W2^T + b2) * h1
            #pragma unroll
            for (int nt = 0; nt < 4; nt++) {
                C[nt][0] = bia2[nt][0]; C[nt][1] = bia2[nt][1];
                C[nt][2] = bia2[nt][0]; C[nt][3] = bia2[nt][1];
                mma_bf16(C[nt], A[0][0], A[0][1], A[0][2], A[0][3], B2[0][nt][0], B2[0][nt][1]);
                mma_bf16(C[nt], A[1][0], A[1][1], A[1][2], A[1][3], B2[1][nt][0], B2[1][nt][1]);
            }
            #pragma unroll
            for (int q = 0; q < 16; q++) h1r[q] = lrelu(C[q >> 2][q & 3]) * h1r[q];
            #pragma unroll
            for (int ks = 0; ks < 2; ks++)
                #pragma unroll
                for (int q = 0; q < 4; q++)
                    A[ks][q] = cvt2(h1r[8 * ks + 2 * q], h1r[8 * ks + 2 * q + 1]);

            // Layer 3: g = lrelu(h @ Wd1^T + bd1)
            #pragma unroll
            for (int nt = 0; nt < 4; nt++) {
                C[nt][0] = bia3[nt][0]; C[nt][1] = bia3[nt][1];
                C[nt][2] = bia3[nt][0]; C[nt][3] = bia3[nt][1];
                mma_bf16(C[nt], A[0][0], A[0][1], A[0][2], A[0][3], B3[0][nt][0], B3[0][nt][1]);
                mma_bf16(C[nt], A[1][0], A[1][1], A[1][2], A[1][3], B3[1][nt][0], B3[1][nt][1]);
            }
            #pragma unroll
            for (int q = 0; q < 16; q++) h1r[q] = lrelu(C[q >> 2][q & 3]);
            #pragma unroll
            for (int ks = 0; ks < 2; ks++)
                #pragma unroll
                for (int q = 0; q < 4; q++)
                    A[ks][q] = cvt2(h1r[8 * ks + 2 * q], h1r[8 * ks + 2 * q + 1]);

            // Layer 4: y = g @ Wd2^T + bd2 (single n8 tile, cols 0..2 valid)
            float C4[4];
            C4[0] = bia4[0]; C4[1] = bia4[1]; C4[2] = bia4[0]; C4[3] = bia4[1];
            mma_bf16(C4, A[0][0], A[0][1], A[0][2], A[0][3], B4[0][0], B4[0][1]);
            mma_bf16(C4, A[1][0], A[1][1], A[1][2], A[1][3], B4[1][0], B4[1][1]);

            if ((lane & 3) == 0) {
                sy[warp][r1][0] = C4[0]; sy[warp][r1][1] = C4[1];
                sy[warp][r2][0] = C4[2]; sy[warp][r2][1] = C4[3];
            } else if ((lane & 3) == 1) {
                sy[warp][r1][2] = C4[0];
                sy[warp][r2][2] = C4[2];
            }
        }
        __syncwarp();

        // ---- epilogue: rotate with this lane's own frame (row = rowbase+lane) ----
        if (ok) {
            const float y0 = sy[warp][lane][0];
            const float y1 = sy[warp][lane][1];
            const float y2 = sy[warp][lane][2];
            out[row * 3 + 0] = fmaf(v0, y0, fmaf(w0, y1, fmaf(u0, y2, bs0)));
            out[row * 3 + 1] = fmaf(v1, y0, fmaf(w1, y1, fmaf(u1, y2, bs1)));
            out[row * 3 + 2] = fmaf(v2, y0, fmaf(w2, y1, fmaf(u2, y2, bs2)));
        }
        __syncwarp();
    }
}

extern "C" void kernel_launch(void* const* d_in, const int* in_sizes, int n_in,
                              void* d_out, int out_size)
{
    const float* v    = (const float*)d_in[0];
    const float* w    = (const float*)d_in[1];
    const float* W1   = (const float*)d_in[2];
    const float* b1   = (const float*)d_in[3];
    const float* W2   = (const float*)d_in[4];
    const float* b2   = (const float*)d_in[5];
    const float* Wd1  = (const float*)d_in[6];
    const float* bd1  = (const float*)d_in[7];
    const float* Wd2  = (const float*)d_in[8];
    const float* bd2  = (const float*)d_in[9];
    const float* bias = (const float*)d_in[10];
    float* out = (float*)d_out;

    const int n = in_sizes[0] / 3;
    const long tiles = ((long)n + 31) / 32;
    const long warps = (tiles + TILES_PER_WARP - 1) / TILES_PER_WARP;
    const int blocks = (int)((warps + WARPS_PER_CTA - 1) / WARPS_PER_CTA);
    aero_kernel<<<blocks, WARPS_PER_CTA * 32>>>(v, w, W1, b1, W2, b2, Wd1, bd1,
                                               Wd2, bd2, bias, out, n);
}

// round 9
// speedup vs baseline: 4.9292x; 1.1160x over previous
#include <cuda_runtime.h>

#define EPSV  1e-8f
#define SLOPE 0.01f
#define HID   32
#define TILES_PER_WARP 4
#define WARPS_PER_CTA  8

__device__ __forceinline__ float lrelu(float x) { return fmaxf(x, SLOPE * x); }

// pack {lo=x, hi=y} as bf16x2 (first PTX source -> high half)
__device__ __forceinline__ unsigned cvt2(float lo, float hi) {
    unsigned r;
    asm("cvt.rn.bf16x2.f32 %0, %1, %2;" : "=r"(r) : "f"(hi), "f"(lo));
    return r;
}

__device__ __forceinline__ void mma_bf16(float c[4],
                                         unsigned a0, unsigned a1, unsigned a2, unsigned a3,
                                         unsigned b0, unsigned b1) {
    asm("mma.sync.aligned.m16n8k16.row.col.f32.bf16.bf16.f32 "
        "{%0,%1,%2,%3},{%4,%5,%6,%7},{%8,%9},{%0,%1,%2,%3};"
        : "+f"(c[0]), "+f"(c[1]), "+f"(c[2]), "+f"(c[3])
        : "r"(a0), "r"(a1), "r"(a2), "r"(a3), "r"(b0), "r"(b1));
}

__global__ __launch_bounds__(WARPS_PER_CTA * 32, 2)
void aero_kernel(const float* __restrict__ v, const float* __restrict__ w,
                 const float* __restrict__ W1, const float* __restrict__ b1,
                 const float* __restrict__ W2, const float* __restrict__ b2,
                 const float* __restrict__ Wd1, const float* __restrict__ bd1,
                 const float* __restrict__ Wd2, const float* __restrict__ bd2,
                 const float* __restrict__ bias,
                 float* __restrict__ out, int n)
{
    __shared__ float sfeat[WARPS_PER_CTA][32][3];
    __shared__ float sy[WARPS_PER_CTA][32][3];
    __shared__ float sb2s[HID], sbd1s[HID];

    const int lane = threadIdx.x & 31;
    const int warp = threadIdx.x >> 5;
    const long gwarp = (long)blockIdx.x * WARPS_PER_CTA + warp;

    if (threadIdx.x < HID)            sb2s[threadIdx.x] = b2[threadIdx.x];
    else if (threadIdx.x < 2 * HID)   sbd1s[threadIdx.x - HID] = bd1[threadIdx.x - HID];
    __syncthreads();

    const int jn = lane >> 2;        // n-index within an n8 tile (0..7)
    const int kk = (lane & 3) * 2;   // k-pair base within k16 step
    const int cc = (lane & 3) * 2;   // col-pair base of C fragment

    // ================= per-warp weight fragment build (once) =================
    // Layer 1: B[k][n] = W1[n][k], K padded 3->16; k=3 row carries b1 (bias fold,
    // feat[3] is set to 1.0 in the A fragment).
    unsigned B1[4];
    #pragma unroll
    for (int nt = 0; nt < 4; nt++) {
        const int j = 8 * nt + jn;
        float x = 0.0f, y = 0.0f;
        if (kk == 0)      { x = W1[j * 3 + 0]; y = W1[j * 3 + 1]; }
        else if (kk == 2) { x = W1[j * 3 + 2]; y = b1[j]; }
        B1[nt] = cvt2(x, y);
    }
    // Layers 2/3: B[k][n] = W[n][k], 32x32
    unsigned B2[2][4][2], B3[2][4][2];
    #pragma unroll
    for (int ks = 0; ks < 2; ks++)
        #pragma unroll
        for (int nt = 0; nt < 4; nt++) {
            const int j = 8 * nt + jn;
            const int k0 = 16 * ks + kk;
            B2[ks][nt][0] = cvt2(W2[j * HID + k0],     W2[j * HID + k0 + 1]);
            B2[ks][nt][1] = cvt2(W2[j * HID + k0 + 8], W2[j * HID + k0 + 9]);
            B3[ks][nt][0] = cvt2(Wd1[j * HID + k0],     Wd1[j * HID + k0 + 1]);
            B3[ks][nt][1] = cvt2(Wd1[j * HID + k0 + 8], Wd1[j * HID + k0 + 9]);
        }
    // Layer 4: B[k][n] = Wd2[n][k], n padded 3->8
    unsigned B4[2][2];
    #pragma unroll
    for (int ks = 0; ks < 2; ks++) {
        const int k0 = 16 * ks + kk;
        const float x0 = (jn < 3) ? Wd2[jn * HID + k0]     : 0.0f;
        const float x1 = (jn < 3) ? Wd2[jn * HID + k0 + 1] : 0.0f;
        const float x2 = (jn < 3) ? Wd2[jn * HID + k0 + 8] : 0.0f;
        const float x3 = (jn < 3) ? Wd2[jn * HID + k0 + 9] : 0.0f;
        B4[ks][0] = cvt2(x0, x1);
        B4[ks][1] = cvt2(x2, x3);
    }
    float bia4_0 = (cc     < 3) ? bd2[cc]     : 0.0f;
    float bia4_1 = (cc + 1 < 3) ? bd2[cc + 1] : 0.0f;
    const float bs0 = bias[0], bs1 = bias[1], bs2 = bias[2];

    // ============================ main tile loop ============================
    for (int t = 0; t < TILES_PER_WARP; t++) {
        const long rowbase = (gwarp * TILES_PER_WARP + t) * 32;
        if (rowbase >= n) break;
        const long row = rowbase + lane;
        const bool ok = row < n;

        // ---- Gram-Schmidt for row = rowbase + lane (one row per lane) ----
        float vx = 0, vy = 0, vz = 0, wx = 0, wy = 0, wz = 0;
        if (ok) {
            vx = v[row * 3 + 0]; vy = v[row * 3 + 1]; vz = v[row * 3 + 2];
            wx = w[row * 3 + 0]; wy = w[row * 3 + 1]; wz = w[row * 3 + 2];
        }
        const float nv = sqrtf(fmaf(vx, vx, fmaf(vy, vy, vz * vz)));
        const float iv = 1.0f / (nv + EPSV);
        const float v0 = vx * iv, v1 = vy * iv, v2 = vz * iv;
        const float d  = fmaf(wx, v0, fmaf(wy, v1, wz * v2));
        const float ox = fmaf(-d, v0, wx);
        const float oy = fmaf(-d, v1, wy);
        const float oz = fmaf(-d, v2, wz);
        const float nw = sqrtf(fmaf(ox, ox, fmaf(oy, oy, oz * oz)));
        const float iw = 1.0f / (nw + EPSV);
        const float w0 = ox * iw, w1 = oy * iw, w2 = oz * iw;
        const float u0 = fmaf(v1, w2, -v2 * w1);
        const float u1 = fmaf(v2, w0, -v0 * w2);
        const float u2 = fmaf(v0, w1, -v1 * w0);

        sfeat[warp][lane][0] = fmaf(vx, v0, fmaf(vy, v1, vz * v2)); // f0
        sfeat[warp][lane][1] = d;                                   // f1
        sfeat[warp][lane][2] = fmaf(wx, w0, fmaf(wy, w1, wz * w2)); // f2
        __syncwarp();

        // ---- two 16-row MMA tiles ----
        #pragma unroll
        for (int mt = 0; mt < 2; mt++) {
            const int r1 = mt * 16 + (lane >> 2);
            const int r2 = r1 + 8;

            // Layer 1: A from feat (K=3 + bias-lane 1.0 padded into one k16 step)
            unsigned a0 = 0, a1 = 0;
            if ((lane & 3) == 0) {
                a0 = cvt2(sfeat[warp][r1][0], sfeat[warp][r1][1]);
                a1 = cvt2(sfeat[warp][r2][0], sfeat[warp][r2][1]);
            } else if ((lane & 3) == 1) {
                a0 = cvt2(sfeat[warp][r1][2], 1.0f);   // feat[3]=1 -> +b1
                a1 = cvt2(sfeat[warp][r2][2], 1.0f);
            }
            float C[4][4];
            #pragma unroll
            for (int nt = 0; nt < 4; nt++) {
                C[nt][0] = 0.f; C[nt][1] = 0.f; C[nt][2] = 0.f; C[nt][3] = 0.f;
                mma_bf16(C[nt], a0, a1, 0u, 0u, B1[nt], 0u);
            }
            float h1r[16];
            #pragma unroll
            for (int q = 0; q < 16; q++) h1r[q] = lrelu(C[q >> 2][q & 3]);

            unsigned A[2][4];
            #pragma unroll
            for (int ks = 0; ks < 2; ks++)
                #pragma unroll
                for (int q = 0; q < 4; q++)
                    A[ks][q] = cvt2(h1r[8 * ks + 2 * q], h1r[8 * ks + 2 * q + 1]);

            // Layer 2: h = lrelu(h1 @ W2^T + b2) * h1   (bias from shared)
            #pragma unroll
            for (int nt = 0; nt < 4; nt++) {
                const float2 bb = *reinterpret_cast<const float2*>(&sb2s[8 * nt + cc]);
                C[nt][0] = bb.x; C[nt][1] = bb.y; C[nt][2] = bb.x; C[nt][3] = bb.y;
                mma_bf16(C[nt], A[0][0], A[0][1], A[0][2], A[0][3], B2[0][nt][0], B2[0][nt][1]);
                mma_bf16(C[nt], A[1][0], A[1][1], A[1][2], A[1][3], B2[1][nt][0], B2[1][nt][1]);
            }
            #pragma unroll
            for (int q = 0; q < 16; q++) h1r[q] = lrelu(C[q >> 2][q & 3]) * h1r[q];
            #pragma unroll
            for (int ks = 0; ks < 2; ks++)
                #pragma unroll
                for (int q = 0; q < 4; q++)
                    A[ks][q] = cvt2(h1r[8 * ks + 2 * q], h1r[8 * ks + 2 * q + 1]);

            // Layer 3: g = lrelu(h @ Wd1^T + bd1)   (bias from shared)
            #pragma unroll
            for (int nt = 0; nt < 4; nt++) {
                const float2 bb = *reinterpret_cast<const float2*>(&sbd1s[8 * nt + cc]);
                C[nt][0] = bb.x; C[nt][1] = bb.y; C[nt][2] = bb.x; C[nt][3] = bb.y;
                mma_bf16(C[nt], A[0][0], A[0][1], A[0][2], A[0][3], B3[0][nt][0], B3[0][nt][1]);
                mma_bf16(C[nt], A[1][0], A[1][1], A[1][2], A[1][3], B3[1][nt][0], B3[1][nt][1]);
            }
            #pragma unroll
            for (int q = 0; q < 16; q++) h1r[q] = lrelu(C[q >> 2][q & 3]);
            #pragma unroll
            for (int ks = 0; ks < 2; ks++)
                #pragma unroll
                for (int q = 0; q < 4; q++)
                    A[ks][q] = cvt2(h1r[8 * ks + 2 * q], h1r[8 * ks + 2 * q + 1]);

            // Layer 4: y = g @ Wd2^T + bd2 (single n8 tile, cols 0..2 valid)
            float C4[4];
            C4[0] = bia4_0; C4[1] = bia4_1; C4[2] = bia4_0; C4[3] = bia4_1;
            mma_bf16(C4, A[0][0], A[0][1], A[0][2], A[0][3], B4[0][0], B4[0][1]);
            mma_bf16(C4, A[1][0], A[1][1], A[1][2], A[1][3], B4[1][0], B4[1][1]);

            if ((lane & 3) == 0) {
                sy[warp][r1][0] = C4[0]; sy[warp][r1][1] = C4[1];
                sy[warp][r2][0] = C4[2]; sy[warp][r2][1] = C4[3];
            } else if ((lane & 3) == 1) {
                sy[warp][r1][2] = C4[0];
                sy[warp][r2][2] = C4[2];
            }
        }
        __syncwarp();

        // ---- epilogue: rotate with this lane's own frame (row = rowbase+lane) ----
        if (ok) {
            const float y0 = sy[warp][lane][0];
            const float y1 = sy[warp][lane][1];
            const float y2 = sy[warp][lane][2];
            out[row * 3 + 0] = fmaf(v0, y0, fmaf(w0, y1, fmaf(u0, y2, bs0)));
            out[row * 3 + 1] = fmaf(v1, y0, fmaf(w1, y1, fmaf(u1, y2, bs1)));
            out[row * 3 + 2] = fmaf(v2, y0, fmaf(w2, y1, fmaf(u2, y2, bs2)));
        }
        __syncwarp();
    }
}

extern "C" void kernel_launch(void* const* d_in, const int* in_sizes, int n_in,
                              void* d_out, int out_size)
{
    const float* v    = (const float*)d_in[0];
    const float* w    = (const float*)d_in[1];
    const float* W1   = (const float*)d_in[2];
    const float* b1   = (const float*)d_in[3];
    const float* W2   = (const float*)d_in[4];
    const float* b2   = (const float*)d_in[5];
    const float* Wd1  = (const float*)d_in[6];
    const float* bd1  = (const float*)d_in[7];
    const float* Wd2  = (const float*)d_in[8];
    const float* bd2  = (const float*)d_in[9];
    const float* bias = (const float*)d_in[10];
    float* out = (float*)d_out;

    const int n = in_sizes[0] / 3;
    const long tiles = ((long)n + 31) / 32;
    const long warps = (tiles + TILES_PER_WARP - 1) / TILES_PER_WARP;
    const int blocks = (int)((warps + WARPS_PER_CTA - 1) / WARPS_PER_CTA);
    aero_kernel<<<blocks, WARPS_PER_CTA * 32>>>(v, w, W1, b1, W2, b2, Wd1, bd1,
                                               Wd2, bd2, bias, out, n);
}

// round 13
// speedup vs baseline: 5.3497x; 1.0853x over previous
#include <cuda_runtime.h>
#include <cuda_bf16.h>

#define SLOPE 0.01f
#define HID   32
#define TILES_PER_WARP 4
#define WARPS_PER_CTA  8

__device__ __forceinline__ unsigned cvt2(float lo, float hi) {
    unsigned r;
    asm("cvt.rn.bf16x2.f32 %0, %1, %2;" : "=r"(r) : "f"(hi), "f"(lo));
    return r;
}
__device__ __forceinline__ __nv_bfloat162 as_b(unsigned u) { return *reinterpret_cast<__nv_bfloat162*>(&u); }
__device__ __forceinline__ unsigned as_u(__nv_bfloat162 b) { return *reinterpret_cast<unsigned*>(&b); }

// packed leaky-relu: max(x, slope*x) elementwise in bf16x2
__device__ __forceinline__ unsigned lrelu2(unsigned x, __nv_bfloat162 sl) {
    return as_u(__hmax2(as_b(x), __hmul2(as_b(x), sl)));
}
__device__ __forceinline__ unsigned mul2u(unsigned a, unsigned b) {
    return as_u(__hmul2(as_b(a), as_b(b)));
}

__device__ __forceinline__ void mma_bf16(float c[4],
                                         unsigned a0, unsigned a1, unsigned a2, unsigned a3,
                                         unsigned b0, unsigned b1) {
    asm("mma.sync.aligned.m16n8k16.row.col.f32.bf16.bf16.f32 "
        "{%0,%1,%2,%3},{%4,%5,%6,%7},{%8,%9},{%0,%1,%2,%3};"
        : "+f"(c[0]), "+f"(c[1]), "+f"(c[2]), "+f"(c[3])
        : "r"(a0), "r"(a1), "r"(a2), "r"(a3), "r"(b0), "r"(b1));
}

__global__ __launch_bounds__(WARPS_PER_CTA * 32, 2)
void aero_kernel(const float* __restrict__ v, const float* __restrict__ w,
                 const float* __restrict__ W1, const float* __restrict__ b1,
                 const float* __restrict__ W2, const float* __restrict__ b2,
                 const float* __restrict__ Wd1, const float* __restrict__ bd1,
                 const float* __restrict__ Wd2, const float* __restrict__ bd2,
                 const float* __restrict__ bias,
                 float* __restrict__ out, int n)
{
    __shared__ float sfeat[WARPS_PER_CTA][32][3];
    __shared__ float sy[WARPS_PER_CTA][32][3];
    __shared__ float sb2s[HID], sbd1s[HID];

    const int lane = threadIdx.x & 31;
    const int warp = threadIdx.x >> 5;
    const long gwarp = (long)blockIdx.x * WARPS_PER_CTA + warp;

    if (threadIdx.x < HID)            sb2s[threadIdx.x] = b2[threadIdx.x];
    else if (threadIdx.x < 2 * HID)   sbd1s[threadIdx.x - HID] = bd1[threadIdx.x - HID];
    __syncthreads();

    const int jn = lane >> 2;        // n-index within an n8 tile
    const int kk = (lane & 3) * 2;   // k-pair base
    const int cc = (lane & 3) * 2;   // C col-pair base
    const __nv_bfloat162 sl2 = __float2bfloat162_rn(SLOPE);

    // ================= weight fragments (per warp, once) =================
    // Layer 1: K padded 3->16, k=3 row carries b1 (A supplies 1.0 there)
    unsigned B1[4];
    #pragma unroll
    for (int nt = 0; nt < 4; nt++) {
        const int j = 8 * nt + jn;
        float x = 0.0f, y = 0.0f;
        if (kk == 0)      { x = W1[j * 3 + 0]; y = W1[j * 3 + 1]; }
        else if (kk == 2) { x = W1[j * 3 + 2]; y = b1[j]; }
        B1[nt] = cvt2(x, y);
    }
    unsigned B2[2][4][2], B3[2][4][2];
    #pragma unroll
    for (int ks = 0; ks < 2; ks++)
        #pragma unroll
        for (int nt = 0; nt < 4; nt++) {
            const int j = 8 * nt + jn;
            const int k0 = 16 * ks + kk;
            B2[ks][nt][0] = cvt2(W2[j * HID + k0],     W2[j * HID + k0 + 1]);
            B2[ks][nt][1] = cvt2(W2[j * HID + k0 + 8], W2[j * HID + k0 + 9]);
            B3[ks][nt][0] = cvt2(Wd1[j * HID + k0],     Wd1[j * HID + k0 + 1]);
            B3[ks][nt][1] = cvt2(Wd1[j * HID + k0 + 8], Wd1[j * HID + k0 + 9]);
        }
    unsigned B4[2][2];
    #pragma unroll
    for (int ks = 0; ks < 2; ks++) {
        const int k0 = 16 * ks + kk;
        const float x0 = (jn < 3) ? Wd2[jn * HID + k0]     : 0.0f;
        const float x1 = (jn < 3) ? Wd2[jn * HID + k0 + 1] : 0.0f;
        const float x2 = (jn < 3) ? Wd2[jn * HID + k0 + 8] : 0.0f;
        const float x3 = (jn < 3) ? Wd2[jn * HID + k0 + 9] : 0.0f;
        B4[ks][0] = cvt2(x0, x1);
        B4[ks][1] = cvt2(x2, x3);
    }
    const float bia4_0 = (cc     < 3) ? bd2[cc]     : 0.0f;
    const float bia4_1 = (cc + 1 < 3) ? bd2[cc + 1] : 0.0f;
    const float bs0 = bias[0], bs1 = bias[1], bs2 = bias[2];

    // ============================ main tile loop ============================
    for (int t = 0; t < TILES_PER_WARP; t++) {
        const long rowbase = (gwarp * TILES_PER_WARP + t) * 32;
        if (rowbase >= n) break;
        const long row = rowbase + lane;
        const bool ok = row < n;

        // ---- Gram-Schmidt, one row per lane ----
        float vx = 0, vy = 0, vz = 0, wx = 0, wy = 0, wz = 0;
        if (ok) {
            vx = v[row * 3 + 0]; vy = v[row * 3 + 1]; vz = v[row * 3 + 2];
            wx = w[row * 3 + 0]; wy = w[row * 3 + 1]; wz = w[row * 3 + 2];
        }
        const float sv = fmaf(vx, vx, fmaf(vy, vy, vz * vz));
        const float iv = rsqrtf(fmaxf(sv, 1e-35f));
        const float v0 = vx * iv, v1 = vy * iv, v2 = vz * iv;
        const float d  = fmaf(wx, v0, fmaf(wy, v1, wz * v2));
        const float ox = fmaf(-d, v0, wx);
        const float oy = fmaf(-d, v1, wy);
        const float oz = fmaf(-d, v2, wz);
        const float sw = fmaf(ox, ox, fmaf(oy, oy, oz * oz));
        const float iw = rsqrtf(fmaxf(sw, 1e-35f));
        const float w0 = ox * iw, w1 = oy * iw, w2 = oz * iw;
        const float u0 = fmaf(v1, w2, -v2 * w1);
        const float u1 = fmaf(v2, w0, -v0 * w2);
        const float u2 = fmaf(v0, w1, -v1 * w0);

        sfeat[warp][lane][0] = fmaf(vx, v0, fmaf(vy, v1, vz * v2)); // f0
        sfeat[warp][lane][1] = d;                                   // f1
        sfeat[warp][lane][2] = fmaf(wx, w0, fmaf(wy, w1, wz * w2)); // f2
        __syncwarp();

        // ---- layer 1 for BOTH 16-row tiles (8 MMAs in flight) ----
        float C[2][4][4];
        {
            unsigned a0[2], a1[2];
            #pragma unroll
            for (int mt = 0; mt < 2; mt++) {
                const int r1 = mt * 16 + (lane >> 2);
                const int r2 = r1 + 8;
                unsigned x0 = 0, x1 = 0;
                if ((lane & 3) == 0) {
                    x0 = cvt2(sfeat[warp][r1][0], sfeat[warp][r1][1]);
                    x1 = cvt2(sfeat[warp][r2][0], sfeat[warp][r2][1]);
                } else if ((lane & 3) == 1) {
                    x0 = cvt2(sfeat[warp][r1][2], 1.0f);   // k=3 lane -> +b1
                    x1 = cvt2(sfeat[warp][r2][2], 1.0f);
                }
                a0[mt] = x0; a1[mt] = x1;
            }
            #pragma unroll
            for (int mt = 0; mt < 2; mt++)
                #pragma unroll
                for (int nt = 0; nt < 4; nt++) {
                    C[mt][nt][0] = 0.f; C[mt][nt][1] = 0.f;
                    C[mt][nt][2] = 0.f; C[mt][nt][3] = 0.f;
                    mma_bf16(C[mt][nt], a0[mt], a1[mt], 0u, 0u, B1[nt], 0u);
                }
        }
        // epilogue 1: h1p = lrelu2(pack(C))   [mt][nt][j], j=0 -> rows r1, j=1 -> rows r2
        unsigned h1p[2][4][2];
        #pragma unroll
        for (int mt = 0; mt < 2; mt++)
            #pragma unroll
            for (int nt = 0; nt < 4; nt++) {
                h1p[mt][nt][0] = lrelu2(cvt2(C[mt][nt][0], C[mt][nt][1]), sl2);
                h1p[mt][nt][1] = lrelu2(cvt2(C[mt][nt][2], C[mt][nt][3]), sl2);
            }

        // ---- layer 2 ----
        #pragma unroll
        for (int mt = 0; mt < 2; mt++)
            #pragma unroll
            for (int nt = 0; nt < 4; nt++) {
                const float2 bb = *reinterpret_cast<const float2*>(&sb2s[8 * nt + cc]);
                C[mt][nt][0] = bb.x; C[mt][nt][1] = bb.y;
                C[mt][nt][2] = bb.x; C[mt][nt][3] = bb.y;
                mma_bf16(C[mt][nt], h1p[mt][0][0], h1p[mt][0][1], h1p[mt][1][0], h1p[mt][1][1],
                         B2[0][nt][0], B2[0][nt][1]);
                mma_bf16(C[mt][nt], h1p[mt][2][0], h1p[mt][2][1], h1p[mt][3][0], h1p[mt][3][1],
                         B2[1][nt][0], B2[1][nt][1]);
            }
        // epilogue 2: A = lrelu2(pack(C)) * h1p   (gate), overwrite h1p
        #pragma unroll
        for (int mt = 0; mt < 2; mt++)
            #pragma unroll
            for (int nt = 0; nt < 4; nt++) {
                h1p[mt][nt][0] = mul2u(lrelu2(cvt2(C[mt][nt][0], C[mt][nt][1]), sl2), h1p[mt][nt][0]);
                h1p[mt][nt][1] = mul2u(lrelu2(cvt2(C[mt][nt][2], C[mt][nt][3]), sl2), h1p[mt][nt][1]);
            }

        // ---- layer 3 ----
        #pragma unroll
        for (int mt = 0; mt < 2; mt++)
            #pragma unroll
            for (int nt = 0; nt < 4; nt++) {
                const float2 bb = *reinterpret_cast<const float2*>(&sbd1s[8 * nt + cc]);
                C[mt][nt][0] = bb.x; C[mt][nt][1] = bb.y;
                C[mt][nt][2] = bb.x; C[mt][nt][3] = bb.y;
                mma_bf16(C[mt][nt], h1p[mt][0][0], h1p[mt][0][1], h1p[mt][1][0], h1p[mt][1][1],
                         B3[0][nt][0], B3[0][nt][1]);
                mma_bf16(C[mt][nt], h1p[mt][2][0], h1p[mt][2][1], h1p[mt][3][0], h1p[mt][3][1],
                         B3[1][nt][0], B3[1][nt][1]);
            }
        // epilogue 3: A = lrelu2(pack(C))
        #pragma unroll
        for (int mt = 0; mt < 2; mt++)
            #pragma unroll
            for (int nt = 0; nt < 4; nt++) {
                h1p[mt][nt][0] = lrelu2(cvt2(C[mt][nt][0], C[mt][nt][1]), sl2);
                h1p[mt][nt][1] = lrelu2(cvt2(C[mt][nt][2], C[mt][nt][3]), sl2);
            }

        // ---- layer 4 (one n8 tile per mt) + scatter y to smem ----
        #pragma unroll
        for (int mt = 0; mt < 2; mt++) {
            float C4[4];
            C4[0] = bia4_0; C4[1] = bia4_1; C4[2] = bia4_0; C4[3] = bia4_1;
            mma_bf16(C4, h1p[mt][0][0], h1p[mt][0][1], h1p[mt][1][0], h1p[mt][1][1],
                     B4[0][0], B4[0][1]);
            mma_bf16(C4, h1p[mt][2][0], h1p[mt][2][1], h1p[mt][3][0], h1p[mt][3][1],
                     B4[1][0], B4[1][1]);
            const int r1 = mt * 16 + (lane >> 2);
            const int r2 = r1 + 8;
            if ((lane & 3) == 0) {
                sy[warp][r1][0] = C4[0]; sy[warp][r1][1] = C4[1];
                sy[warp][r2][0] = C4[2]; sy[warp][r2][1] = C4[3];
            } else if ((lane & 3) == 1) {
                sy[warp][r1][2] = C4[0];
                sy[warp][r2][2] = C4[2];
            }
        }
        __syncwarp();

        // ---- epilogue: rotate with this lane's own frame ----
        if (ok) {
            const float y0 = sy[warp][lane][0];
            const float y1 = sy[warp][lane][1];
            const float y2 = sy[warp][lane][2];
            out[row * 3 + 0] = fmaf(v0, y0, fmaf(w0, y1, fmaf(u0, y2, bs0)));
            out[row * 3 + 1] = fmaf(v1, y0, fmaf(w1, y1, fmaf(u1, y2, bs1)));
            out[row * 3 + 2] = fmaf(v2, y0, fmaf(w2, y1, fmaf(u2, y2, bs2)));
        }
        __syncwarp();
    }
}

extern "C" void kernel_launch(void* const* d_in, const int* in_sizes, int n_in,
                              void* d_out, int out_size)
{
    const float* v    = (const float*)d_in[0];
    const float* w    = (const float*)d_in[1];
    const float* W1   = (const float*)d_in[2];
    const float* b1   = (const float*)d_in[3];
    const float* W2   = (const float*)d_in[4];
    const float* b2   = (const float*)d_in[5];
    const float* Wd1  = (const float*)d_in[6];
    const float* bd1  = (const float*)d_in[7];
    const float* Wd2  = (const float*)d_in[8];
    const float* bd2  = (const float*)d_in[9];
    const float* bias = (const float*)d_in[10];
    float* out = (float*)d_out;

    const int n = in_sizes[0] / 3;
    const long tiles = ((long)n + 31) / 32;
    const long warps = (tiles + TILES_PER_WARP - 1) / TILES_PER_WARP;
    const int blocks = (int)((warps + WARPS_PER_CTA - 1) / WARPS_PER_CTA);
    aero_kernel<<<blocks, WARPS_PER_CTA * 32>>>(v, w, W1, b1, W2, b2, Wd1, bd1,
                                               Wd2, bd2, bias, out, n);
}

// round 14
// speedup vs baseline: 7.2435x; 1.3540x over previous
#include <cuda_runtime.h>
#include <cuda_bf16.h>

#define SLOPE 0.01f
#define HID   32
#define TILES_PER_WARP 4
#define WARPS_PER_CTA  8

__device__ __forceinline__ unsigned cvt2(float lo, float hi) {
    unsigned r;
    asm("cvt.rn.bf16x2.f32 %0, %1, %2;" : "=r"(r) : "f"(hi), "f"(lo));
    return r;
}
__device__ __forceinline__ __nv_bfloat162 as_b(unsigned u) { return *reinterpret_cast<__nv_bfloat162*>(&u); }
__device__ __forceinline__ unsigned as_u(__nv_bfloat162 b) { return *reinterpret_cast<unsigned*>(&b); }

__device__ __forceinline__ unsigned lrelu2(unsigned x, __nv_bfloat162 sl) {
    return as_u(__hmax2(as_b(x), __hmul2(as_b(x), sl)));
}
__device__ __forceinline__ unsigned mul2u(unsigned a, unsigned b) {
    return as_u(__hmul2(as_b(a), as_b(b)));
}

__device__ __forceinline__ void mma_bf16(float c[4],
                                         unsigned a0, unsigned a1, unsigned a2, unsigned a3,
                                         unsigned b0, unsigned b1) {
    asm("mma.sync.aligned.m16n8k16.row.col.f32.bf16.bf16.f32 "
        "{%0,%1,%2,%3},{%4,%5,%6,%7},{%8,%9},{%0,%1,%2,%3};"
        : "+f"(c[0]), "+f"(c[1]), "+f"(c[2]), "+f"(c[3])
        : "r"(a0), "r"(a1), "r"(a2), "r"(a3), "r"(b0), "r"(b1));
}

__global__ __launch_bounds__(WARPS_PER_CTA * 32, 2)
void aero_kernel(const float* __restrict__ v, const float* __restrict__ w,
                 const float* __restrict__ W1, const float* __restrict__ b1,
                 const float* __restrict__ W2, const float* __restrict__ b2,
                 const float* __restrict__ Wd1, const float* __restrict__ bd1,
                 const float* __restrict__ Wd2, const float* __restrict__ bd2,
                 const float* __restrict__ bias,
                 float* __restrict__ out, int n)
{
    __shared__ float sfeat[WARPS_PER_CTA][32][3];
    __shared__ float sy[WARPS_PER_CTA][32][3];
    __shared__ float sb2s[HID], sbd1s[HID];
    // Warp-invariant weight fragments, one word per lane:
    // index ((ks*4 + nt)*2 + j)*32 + lane,  j selects b0/b1 of the MMA.
    __shared__ unsigned sB2[2 * 4 * 2 * 32];
    __shared__ unsigned sB3[2 * 4 * 2 * 32];

    const int lane = threadIdx.x & 31;
    const int warp = threadIdx.x >> 5;
    const long gwarp = (long)blockIdx.x * WARPS_PER_CTA + warp;

    if (threadIdx.x < HID)            sb2s[threadIdx.x] = b2[threadIdx.x];
    else if (threadIdx.x < 2 * HID)   sbd1s[threadIdx.x - HID] = bd1[threadIdx.x - HID];

    // ---- build shared weight-fragment tables (distributed over CTA) ----
    for (int idx = threadIdx.x; idx < 2 * 4 * 2 * 32; idx += WARPS_PER_CTA * 32) {
        const int ln   = idx & 31;
        const int rest = idx >> 5;
        const int j    = rest & 1;          // 0 -> b0 (k+0..1), 1 -> b1 (k+8..9)
        const int nt   = (rest >> 1) & 3;
        const int ks   = rest >> 3;
        const int jrow = 8 * nt + (ln >> 2);
        const int k0   = 16 * ks + (ln & 3) * 2 + (j ? 8 : 0);
        sB2[idx] = cvt2(W2[jrow * HID + k0],  W2[jrow * HID + k0 + 1]);
        sB3[idx] = cvt2(Wd1[jrow * HID + k0], Wd1[jrow * HID + k0 + 1]);
    }
    __syncthreads();

    const int jn = lane >> 2;
    const int kk = (lane & 3) * 2;
    const int cc = (lane & 3) * 2;
    const __nv_bfloat162 sl2 = __float2bfloat162_rn(SLOPE);

    // ---- small persistent fragments (8 regs) ----
    unsigned B1[4];
    #pragma unroll
    for (int nt = 0; nt < 4; nt++) {
        const int j = 8 * nt + jn;
        float x = 0.0f, y = 0.0f;
        if (kk == 0)      { x = W1[j * 3 + 0]; y = W1[j * 3 + 1]; }
        else if (kk == 2) { x = W1[j * 3 + 2]; y = b1[j]; }   // bias fold, A k=3 lane = 1.0
        B1[nt] = cvt2(x, y);
    }
    unsigned B4[2][2];
    #pragma unroll
    for (int ks = 0; ks < 2; ks++) {
        const int k0 = 16 * ks + kk;
        const float x0 = (jn < 3) ? Wd2[jn * HID + k0]     : 0.0f;
        const float x1 = (jn < 3) ? Wd2[jn * HID + k0 + 1] : 0.0f;
        const float x2 = (jn < 3) ? Wd2[jn * HID + k0 + 8] : 0.0f;
        const float x3 = (jn < 3) ? Wd2[jn * HID + k0 + 9] : 0.0f;
        B4[ks][0] = cvt2(x0, x1);
        B4[ks][1] = cvt2(x2, x3);
    }
    const float bia4_0 = (cc     < 3) ? bd2[cc]     : 0.0f;
    const float bia4_1 = (cc + 1 < 3) ? bd2[cc + 1] : 0.0f;
    const float bs0 = bias[0], bs1 = bias[1], bs2 = bias[2];

    // ============================ main tile loop ============================
    for (int t = 0; t < TILES_PER_WARP; t++) {
        const long rowbase = (gwarp * TILES_PER_WARP + t) * 32;
        if (rowbase >= n) break;
        const long row = rowbase + lane;
        const bool ok = row < n;

        // ---- Gram-Schmidt, one row per lane ----
        float vx = 0, vy = 0, vz = 0, wx = 0, wy = 0, wz = 0;
        if (ok) {
            vx = v[row * 3 + 0]; vy = v[row * 3 + 1]; vz = v[row * 3 + 2];
            wx = w[row * 3 + 0]; wy = w[row * 3 + 1]; wz = w[row * 3 + 2];
        }
        const float sv = fmaf(vx, vx, fmaf(vy, vy, vz * vz));
        const float iv = rsqrtf(fmaxf(sv, 1e-35f));
        const float v0 = vx * iv, v1 = vy * iv, v2 = vz * iv;
        const float d  = fmaf(wx, v0, fmaf(wy, v1, wz * v2));
        const float ox = fmaf(-d, v0, wx);
        const float oy = fmaf(-d, v1, wy);
        const float oz = fmaf(-d, v2, wz);
        const float sw = fmaf(ox, ox, fmaf(oy, oy, oz * oz));
        const float iw = rsqrtf(fmaxf(sw, 1e-35f));
        const float w0 = ox * iw, w1 = oy * iw, w2 = oz * iw;
        const float u0 = fmaf(v1, w2, -v2 * w1);
        const float u1 = fmaf(v2, w0, -v0 * w2);
        const float u2 = fmaf(v0, w1, -v1 * w0);

        sfeat[warp][lane][0] = fmaf(vx, v0, fmaf(vy, v1, vz * v2));
        sfeat[warp][lane][1] = d;
        sfeat[warp][lane][2] = fmaf(wx, w0, fmaf(wy, w1, wz * w2));
        __syncwarp();

        // ---- layer 1, both 16-row tiles ----
        float C[2][4][4];
        {
            unsigned a0[2], a1[2];
            #pragma unroll
            for (int mt = 0; mt < 2; mt++) {
                const int r1 = mt * 16 + (lane >> 2);
                const int r2 = r1 + 8;
                unsigned x0 = 0, x1 = 0;
                if ((lane & 3) == 0) {
                    x0 = cvt2(sfeat[warp][r1][0], sfeat[warp][r1][1]);
                    x1 = cvt2(sfeat[warp][r2][0], sfeat[warp][r2][1]);
                } else if ((lane & 3) == 1) {
                    x0 = cvt2(sfeat[warp][r1][2], 1.0f);
                    x1 = cvt2(sfeat[warp][r2][2], 1.0f);
                }
                a0[mt] = x0; a1[mt] = x1;
            }
            #pragma unroll
            for (int mt = 0; mt < 2; mt++)
                #pragma unroll
                for (int nt = 0; nt < 4; nt++) {
                    C[mt][nt][0] = 0.f; C[mt][nt][1] = 0.f;
                    C[mt][nt][2] = 0.f; C[mt][nt][3] = 0.f;
                    mma_bf16(C[mt][nt], a0[mt], a1[mt], 0u, 0u, B1[nt], 0u);
                }
        }
        unsigned h1p[2][4][2];
        #pragma unroll
        for (int mt = 0; mt < 2; mt++)
            #pragma unroll
            for (int nt = 0; nt < 4; nt++) {
                h1p[mt][nt][0] = lrelu2(cvt2(C[mt][nt][0], C[mt][nt][1]), sl2);
                h1p[mt][nt][1] = lrelu2(cvt2(C[mt][nt][2], C[mt][nt][3]), sl2);
            }

        // ---- layer 2 (B from shared, lane-indexed, conflict-free) ----
        #pragma unroll
        for (int mt = 0; mt < 2; mt++)
            #pragma unroll
            for (int nt = 0; nt < 4; nt++) {
                const float2 bb = *reinterpret_cast<const float2*>(&sb2s[8 * nt + cc]);
                C[mt][nt][0] = bb.x; C[mt][nt][1] = bb.y;
                C[mt][nt][2] = bb.x; C[mt][nt][3] = bb.y;
                mma_bf16(C[mt][nt], h1p[mt][0][0], h1p[mt][0][1], h1p[mt][1][0], h1p[mt][1][1],
                         sB2[(nt * 2 + 0) * 32 + lane], sB2[(nt * 2 + 1) * 32 + lane]);
                mma_bf16(C[mt][nt], h1p[mt][2][0], h1p[mt][2][1], h1p[mt][3][0], h1p[mt][3][1],
                         sB2[((4 + nt) * 2 + 0) * 32 + lane], sB2[((4 + nt) * 2 + 1) * 32 + lane]);
            }
        #pragma unroll
        for (int mt = 0; mt < 2; mt++)
            #pragma unroll
            for (int nt = 0; nt < 4; nt++) {
                h1p[mt][nt][0] = mul2u(lrelu2(cvt2(C[mt][nt][0], C[mt][nt][1]), sl2), h1p[mt][nt][0]);
                h1p[mt][nt][1] = mul2u(lrelu2(cvt2(C[mt][nt][2], C[mt][nt][3]), sl2), h1p[mt][nt][1]);
            }

        // ---- layer 3 ----
        #pragma unroll
        for (int mt = 0; mt < 2; mt++)
            #pragma unroll
            for (int nt = 0; nt < 4; nt++) {
                const float2 bb = *reinterpret_cast<const float2*>(&sbd1s[8 * nt + cc]);
                C[mt][nt][0] = bb.x; C[mt][nt][1] = bb.y;
                C[mt][nt][2] = bb.x; C[mt][nt][3] = bb.y;
                mma_bf16(C[mt][nt], h1p[mt][0][0], h1p[mt][0][1], h1p[mt][1][0], h1p[mt][1][1],
                         sB3[(nt * 2 + 0) * 32 + lane], sB3[(nt * 2 + 1) * 32 + lane]);
                mma_bf16(C[mt][nt], h1p[mt][2][0], h1p[mt][2][1], h1p[mt][3][0], h1p[mt][3][1],
                         sB3[((4 + nt) * 2 + 0) * 32 + lane], sB3[((4 + nt) * 2 + 1) * 32 + lane]);
            }
        #pragma unroll
        for (int mt = 0; mt < 2; mt++)
            #pragma unroll
            for (int nt = 0; nt < 4; nt++) {
                h1p[mt][nt][0] = lrelu2(cvt2(C[mt][nt][0], C[mt][nt][1]), sl2);
                h1p[mt][nt][1] = lrelu2(cvt2(C[mt][nt][2], C[mt][nt][3]), sl2);
            }

        // ---- layer 4 + y scatter ----
        #pragma unroll
        for (int mt = 0; mt < 2; mt++) {
            float C4[4];
            C4[0] = bia4_0; C4[1] = bia4_1; C4[2] = bia4_0; C4[3] = bia4_1;
            mma_bf16(C4, h1p[mt][0][0], h1p[mt][0][1], h1p[mt][1][0], h1p[mt][1][1],
                     B4[0][0], B4[0][1]);
            mma_bf16(C4, h1p[mt][2][0], h1p[mt][2][1], h1p[mt][3][0], h1p[mt][3][1],
                     B4[1][0], B4[1][1]);
            const int r1 = mt * 16 + (lane >> 2);
            const int r2 = r1 + 8;
            if ((lane & 3) == 0) {
                sy[warp][r1][0] = C4[0]; sy[warp][r1][1] = C4[1];
                sy[warp][r2][0] = C4[2]; sy[warp][r2][1] = C4[3];
            } else if ((lane & 3) == 1) {
                sy[warp][r1][2] = C4[0];
                sy[warp][r2][2] = C4[2];
            }
        }
        __syncwarp();

        // ---- epilogue: rotate with this lane's own frame ----
        if (ok) {
            const float y0 = sy[warp][lane][0];
            const float y1 = sy[warp][lane][1];
            const float y2 = sy[warp][lane][2];
            out[row * 3 + 0] = fmaf(v0, y0, fmaf(w0, y1, fmaf(u0, y2, bs0)));
            out[row * 3 + 1] = fmaf(v1, y0, fmaf(w1, y1, fmaf(u1, y2, bs1)));
            out[row * 3 + 2] = fmaf(v2, y0, fmaf(w2, y1, fmaf(u2, y2, bs2)));
        }
        __syncwarp();
    }
}

extern "C" void kernel_launch(void* const* d_in, const int* in_sizes, int n_in,
                              void* d_out, int out_size)
{
    const float* v    = (const float*)d_in[0];
    const float* w    = (const float*)d_in[1];
    const float* W1   = (const float*)d_in[2];
    const float* b1   = (const float*)d_in[3];
    const float* W2   = (const float*)d_in[4];
    const float* b2   = (const float*)d_in[5];
    const float* Wd1  = (const float*)d_in[6];
    const float* bd1  = (const float*)d_in[7];
    const float* Wd2  = (const float*)d_in[8];
    const float* bd2  = (const float*)d_in[9];
    const float* bias = (const float*)d_in[10];
    float* out = (float*)d_out;

    const int n = in_sizes[0] / 3;
    const long tiles = ((long)n + 31) / 32;
    const long warps = (tiles + TILES_PER_WARP - 1) / TILES_PER_WARP;
    const int blocks = (int)((warps + WARPS_PER_CTA - 1) / WARPS_PER_CTA);
    aero_kernel<<<blocks, WARPS_PER_CTA * 32>>>(v, w, W1, b1, W2, b2, Wd1, bd1,
                                               Wd2, bd2, bias, out, n);
}

// round 16
// speedup vs baseline: 7.9774x; 1.1013x over previous
#include <cuda_runtime.h>
#include <cuda_bf16.h>

#define SLOPE 0.01f
#define HID   32
#define TILES_PER_WARP 4
#define WARPS_PER_CTA  8

__device__ __forceinline__ unsigned cvt2(float lo, float hi) {
    unsigned r;
    asm("cvt.rn.bf16x2.f32 %0, %1, %2;" : "=r"(r) : "f"(hi), "f"(lo));
    return r;
}
__device__ __forceinline__ __nv_bfloat162 as_b(unsigned u) { return *reinterpret_cast<__nv_bfloat162*>(&u); }
__device__ __forceinline__ unsigned as_u(__nv_bfloat162 b) { return *reinterpret_cast<unsigned*>(&b); }

__device__ __forceinline__ unsigned lrelu2(unsigned x, __nv_bfloat162 sl) {
    return as_u(__hmax2(as_b(x), __hmul2(as_b(x), sl)));
}
__device__ __forceinline__ unsigned mul2u(unsigned a, unsigned b) {
    return as_u(__hmul2(as_b(a), as_b(b)));
}

__device__ __forceinline__ void mma_bf16(float c[4],
                                         unsigned a0, unsigned a1, unsigned a2, unsigned a3,
                                         unsigned b0, unsigned b1) {
    asm("mma.sync.aligned.m16n8k16.row.col.f32.bf16.bf16.f32 "
        "{%0,%1,%2,%3},{%4,%5,%6,%7},{%8,%9},{%0,%1,%2,%3};"
        : "+f"(c[0]), "+f"(c[1]), "+f"(c[2]), "+f"(c[3])
        : "r"(a0), "r"(a1), "r"(a2), "r"(a3), "r"(b0), "r"(b1));
}

__global__ __launch_bounds__(WARPS_PER_CTA * 32, 3)
void aero_kernel(const float* __restrict__ v, const float* __restrict__ w,
                 const float* __restrict__ W1, const float* __restrict__ b1,
                 const float* __restrict__ W2, const float* __restrict__ b2,
                 const float* __restrict__ Wd1, const float* __restrict__ bd1,
                 const float* __restrict__ Wd2, const float* __restrict__ bd2,
                 const float* __restrict__ bias,
                 float* __restrict__ out, int n)
{
    __shared__ float sfeat[WARPS_PER_CTA][32][3];
    __shared__ float sy[WARPS_PER_CTA][32][3];
    __shared__ float sframe[WARPS_PER_CTA][32][6];   // v_on, w_on per row
    __shared__ float sb2s[HID], sbd1s[HID];
    __shared__ float sbd2p[8];                       // bd2 padded 3->8 with zeros
    __shared__ float sbias[3];
    // Warp-invariant weight fragments, one word per lane.
    __shared__ unsigned sB2[2 * 4 * 2 * 32];         // ((ks*4+nt)*2+j)*32+lane
    __shared__ unsigned sB3[2 * 4 * 2 * 32];
    __shared__ unsigned sB1[4 * 32];                 // nt*32+lane
    __shared__ unsigned sB4[2 * 2 * 32];             // (ks*2+j)*32+lane

    const int lane = threadIdx.x & 31;
    const int warp = threadIdx.x >> 5;
    const long gwarp = (long)blockIdx.x * WARPS_PER_CTA + warp;

    if (threadIdx.x < HID)            sb2s[threadIdx.x] = b2[threadIdx.x];
    else if (threadIdx.x < 2 * HID)   sbd1s[threadIdx.x - HID] = bd1[threadIdx.x - HID];
    else if (threadIdx.x < 2 * HID + 8) {
        const int q = threadIdx.x - 2 * HID;
        sbd2p[q] = (q < 3) ? bd2[q] : 0.0f;
    } else if (threadIdx.x < 2 * HID + 11) {
        sbias[threadIdx.x - 2 * HID - 8] = bias[threadIdx.x - 2 * HID - 8];
    }

    // ---- build shared weight-fragment tables (distributed over CTA) ----
    for (int idx = threadIdx.x; idx < 2 * 4 * 2 * 32; idx += WARPS_PER_CTA * 32) {
        const int ln   = idx & 31;
        const int rest = idx >> 5;
        const int j    = rest & 1;
        const int nt   = (rest >> 1) & 3;
        const int ks   = rest >> 3;
        const int jrow = 8 * nt + (ln >> 2);
        const int k0   = 16 * ks + (ln & 3) * 2 + (j ? 8 : 0);
        sB2[idx] = cvt2(W2[jrow * HID + k0],  W2[jrow * HID + k0 + 1]);
        sB3[idx] = cvt2(Wd1[jrow * HID + k0], Wd1[jrow * HID + k0 + 1]);
    }
    // sB1: layer 1, K padded 3->16; the k=3 slot carries b1 (A supplies 1.0 there)
    for (int idx = threadIdx.x; idx < 4 * 32; idx += WARPS_PER_CTA * 32) {
        const int ln = idx & 31;
        const int nt = idx >> 5;
        const int j  = 8 * nt + (ln >> 2);
        const int kb = (ln & 3) * 2;
        float x = 0.0f, y = 0.0f;
        if (kb == 0)      { x = W1[j * 3 + 0]; y = W1[j * 3 + 1]; }
        else if (kb == 2) { x = W1[j * 3 + 2]; y = b1[j]; }
        sB1[idx] = cvt2(x, y);
    }
    // sB4: layer 4, n padded 3->8
    for (int idx = threadIdx.x; idx < 2 * 2 * 32; idx += WARPS_PER_CTA * 32) {
        const int ln = idx & 31;
        const int rest = idx >> 5;
        const int j  = rest & 1;
        const int ks = rest >> 1;
        const int jr = ln >> 2;
        const int k0 = 16 * ks + (ln & 3) * 2 + (j ? 8 : 0);
        const float x0 = (jr < 3) ? Wd2[jr * HID + k0]     : 0.0f;
        const float x1 = (jr < 3) ? Wd2[jr * HID + k0 + 1] : 0.0f;
        sB4[idx] = cvt2(x0, x1);
    }
    __syncthreads();

    const int cc = (lane & 3) * 2;
    const __nv_bfloat162 sl2 = __float2bfloat162_rn(SLOPE);

    // ============================ main tile loop ============================
    for (int t = 0; t < TILES_PER_WARP; t++) {
        const long rowbase = (gwarp * TILES_PER_WARP + t) * 32;
        if (rowbase >= n) break;
        const long row = rowbase + lane;
        const bool ok = row < n;

        // ---- Gram-Schmidt, one row per lane; frame stashed to smem ----
        {
            float vx = 0, vy = 0, vz = 0, wx = 0, wy = 0, wz = 0;
            if (ok) {
                vx = v[row * 3 + 0]; vy = v[row * 3 + 1]; vz = v[row * 3 + 2];
                wx = w[row * 3 + 0]; wy = w[row * 3 + 1]; wz = w[row * 3 + 2];
            }
            const float sv = fmaf(vx, vx, fmaf(vy, vy, vz * vz));
            const float iv = rsqrtf(fmaxf(sv, 1e-35f));
            const float v0 = vx * iv, v1 = vy * iv, v2 = vz * iv;
            const float d  = fmaf(wx, v0, fmaf(wy, v1, wz * v2));
            const float ox = fmaf(-d, v0, wx);
            const float oy = fmaf(-d, v1, wy);
            const float oz = fmaf(-d, v2, wz);
            const float sw = fmaf(ox, ox, fmaf(oy, oy, oz * oz));
            const float iw = rsqrtf(fmaxf(sw, 1e-35f));
            const float w0 = ox * iw, w1 = oy * iw, w2 = oz * iw;

            sframe[warp][lane][0] = v0; sframe[warp][lane][1] = v1; sframe[warp][lane][2] = v2;
            sframe[warp][lane][3] = w0; sframe[warp][lane][4] = w1; sframe[warp][lane][5] = w2;
            sfeat[warp][lane][0] = fmaf(vx, v0, fmaf(vy, v1, vz * v2));
            sfeat[warp][lane][1] = d;
            sfeat[warp][lane][2] = fmaf(wx, w0, fmaf(wy, w1, wz * w2));
        }
        __syncwarp();

        // ---- layer 1, both 16-row tiles ----
        float C[2][4][4];
        {
            unsigned a0[2], a1[2];
            #pragma unroll
            for (int mt = 0; mt < 2; mt++) {
                const int r1 = mt * 16 + (lane >> 2);
                const int r2 = r1 + 8;
                unsigned x0 = 0, x1 = 0;
                if ((lane & 3) == 0) {
                    x0 = cvt2(sfeat[warp][r1][0], sfeat[warp][r1][1]);
                    x1 = cvt2(sfeat[warp][r2][0], sfeat[warp][r2][1]);
                } else if ((lane & 3) == 1) {
                    x0 = cvt2(sfeat[warp][r1][2], 1.0f);
                    x1 = cvt2(sfeat[warp][r2][2], 1.0f);
                }
                a0[mt] = x0; a1[mt] = x1;
            }
            #pragma unroll
            for (int mt = 0; mt < 2; mt++)
                #pragma unroll
                for (int nt = 0; nt < 4; nt++) {
                    C[mt][nt][0] = 0.f; C[mt][nt][1] = 0.f;
                    C[mt][nt][2] = 0.f; C[mt][nt][3] = 0.f;
                    mma_bf16(C[mt][nt], a0[mt], a1[mt], 0u, 0u, sB1[nt * 32 + lane], 0u);
                }
        }
        unsigned h1p[2][4][2];
        #pragma unroll
        for (int mt = 0; mt < 2; mt++)
            #pragma unroll
            for (int nt = 0; nt < 4; nt++) {
                h1p[mt][nt][0] = lrelu2(cvt2(C[mt][nt][0], C[mt][nt][1]), sl2);
                h1p[mt][nt][1] = lrelu2(cvt2(C[mt][nt][2], C[mt][nt][3]), sl2);
            }

        // ---- layer 2 ----
        #pragma unroll
        for (int mt = 0; mt < 2; mt++)
            #pragma unroll
            for (int nt = 0; nt < 4; nt++) {
                const float2 bb = *reinterpret_cast<const float2*>(&sb2s[8 * nt + cc]);
                C[mt][nt][0] = bb.x; C[mt][nt][1] = bb.y;
                C[mt][nt][2] = bb.x; C[mt][nt][3] = bb.y;
                mma_bf16(C[mt][nt], h1p[mt][0][0], h1p[mt][0][1], h1p[mt][1][0], h1p[mt][1][1],
                         sB2[(nt * 2 + 0) * 32 + lane], sB2[(nt * 2 + 1) * 32 + lane]);
                mma_bf16(C[mt][nt], h1p[mt][2][0], h1p[mt][2][1], h1p[mt][3][0], h1p[mt][3][1],
                         sB2[((4 + nt) * 2 + 0) * 32 + lane], sB2[((4 + nt) * 2 + 1) * 32 + lane]);
            }
        #pragma unroll
        for (int mt = 0; mt < 2; mt++)
            #pragma unroll
            for (int nt = 0; nt < 4; nt++) {
                h1p[mt][nt][0] = mul2u(lrelu2(cvt2(C[mt][nt][0], C[mt][nt][1]), sl2), h1p[mt][nt][0]);
                h1p[mt][nt][1] = mul2u(lrelu2(cvt2(C[mt][nt][2], C[mt][nt][3]), sl2), h1p[mt][nt][1]);
            }

        // ---- layer 3 ----
        #pragma unroll
        for (int mt = 0; mt < 2; mt++)
            #pragma unroll
            for (int nt = 0; nt < 4; nt++) {
                const float2 bb = *reinterpret_cast<const float2*>(&sbd1s[8 * nt + cc]);
                C[mt][nt][0] = bb.x; C[mt][nt][1] = bb.y;
                C[mt][nt][2] = bb.x; C[mt][nt][3] = bb.y;
                mma_bf16(C[mt][nt], h1p[mt][0][0], h1p[mt][0][1], h1p[mt][1][0], h1p[mt][1][1],
                         sB3[(nt * 2 + 0) * 32 + lane], sB3[(nt * 2 + 1) * 32 + lane]);
                mma_bf16(C[mt][nt], h1p[mt][2][0], h1p[mt][2][1], h1p[mt][3][0], h1p[mt][3][1],
                         sB3[((4 + nt) * 2 + 0) * 32 + lane], sB3[((4 + nt) * 2 + 1) * 32 + lane]);
            }
        #pragma unroll
        for (int mt = 0; mt < 2; mt++)
            #pragma unroll
            for (int nt = 0; nt < 4; nt++) {
                h1p[mt][nt][0] = lrelu2(cvt2(C[mt][nt][0], C[mt][nt][1]), sl2);
                h1p[mt][nt][1] = lrelu2(cvt2(C[mt][nt][2], C[mt][nt][3]), sl2);
            }

        // ---- layer 4 + y scatter ----
        #pragma unroll
        for (int mt = 0; mt < 2; mt++) {
            float C4[4];
            const float2 b4 = *reinterpret_cast<const float2*>(&sbd2p[cc]);
            C4[0] = b4.x; C4[1] = b4.y; C4[2] = b4.x; C4[3] = b4.y;
            mma_bf16(C4, h1p[mt][0][0], h1p[mt][0][1], h1p[mt][1][0], h1p[mt][1][1],
                     sB4[(0 * 2 + 0) * 32 + lane], sB4[(0 * 2 + 1) * 32 + lane]);
            mma_bf16(C4, h1p[mt][2][0], h1p[mt][2][1], h1p[mt][3][0], h1p[mt][3][1],
                     sB4[(1 * 2 + 0) * 32 + lane], sB4[(1 * 2 + 1) * 32 + lane]);
            const int r1 = mt * 16 + (lane >> 2);
            const int r2 = r1 + 8;
            if ((lane & 3) == 0) {
                sy[warp][r1][0] = C4[0]; sy[warp][r1][1] = C4[1];
                sy[warp][r2][0] = C4[2]; sy[warp][r2][1] = C4[3];
            } else if ((lane & 3) == 1) {
                sy[warp][r1][2] = C4[0];
                sy[warp][r2][2] = C4[2];
            }
        }
        __syncwarp();

        // ---- epilogue: reload frame, recompute u = v_on x w_on, rotate ----
        if (ok) {
            const float v0 = sframe[warp][lane][0], v1 = sframe[warp][lane][1], v2 = sframe[warp][lane][2];
            const float w0 = sframe[warp][lane][3], w1 = sframe[warp][lane][4], w2 = sframe[warp][lane][5];
            const float u0 = fmaf(v1, w2, -v2 * w1);
            const float u1 = fmaf(v2, w0, -v0 * w2);
            const float u2 = fmaf(v0, w1, -v1 * w0);
            const float y0 = sy[warp][lane][0];
            const float y1 = sy[warp][lane][1];
            const float y2 = sy[warp][lane][2];
            out[row * 3 + 0] = fmaf(v0, y0, fmaf(w0, y1, fmaf(u0, y2, sbias[0])));
            out[row * 3 + 1] = fmaf(v1, y0, fmaf(w1, y1, fmaf(u1, y2, sbias[1])));
            out[row * 3 + 2] = fmaf(v2, y0, fmaf(w2, y1, fmaf(u2, y2, sbias[2])));
        }
        __syncwarp();
    }
}

extern "C" void kernel_launch(void* const* d_in, const int* in_sizes, int n_in,
                              void* d_out, int out_size)
{
    const float* v    = (const float*)d_in[0];
    const float* w    = (const float*)d_in[1];
    const float* W1   = (const float*)d_in[2];
    const float* b1   = (const float*)d_in[3];
    const float* W2   = (const float*)d_in[4];
    const float* b2   = (const float*)d_in[5];
    const float* Wd1  = (const float*)d_in[6];
    const float* bd1  = (const float*)d_in[7];
    const float* Wd2  = (const float*)d_in[8];
    const float* bd2  = (const float*)d_in[9];
    const float* bias = (const float*)d_in[10];
    float* out = (float*)d_out;

    const int n = in_sizes[0] / 3;
    const long tiles = ((long)n + 31) / 32;
    const long warps = (tiles + TILES_PER_WARP - 1) / TILES_PER_WARP;
    const int blocks = (int)((warps + WARPS_PER_CTA - 1) / WARPS_PER_CTA);
    aero_kernel<<<blocks, WARPS_PER_CTA * 32>>>(v, w, W1, b1, W2, b2, Wd1, bd1,
                                               Wd2, bd2, bias, out, n);
}

// round 17
// speedup vs baseline: 9.0262x; 1.1315x over previous
#include <cuda_runtime.h>
#include <cuda_fp16.h>

#define SLOPE 0.01f
#define HID   32
#define TILES_PER_WARP 4
#define WARPS_PER_CTA  8

__device__ __forceinline__ unsigned pack_h2(float lo, float hi) {
    __half2 h = __floats2half2_rn(lo, hi);
    return *reinterpret_cast<unsigned*>(&h);
}
__device__ __forceinline__ __half2 as_h(unsigned u) { return *reinterpret_cast<__half2*>(&u); }
__device__ __forceinline__ unsigned as_u(__half2 h) { return *reinterpret_cast<unsigned*>(&h); }

__device__ __forceinline__ unsigned lrelu2(unsigned x, __half2 sl) {
    return as_u(__hmax2(as_h(x), __hmul2(as_h(x), sl)));
}
__device__ __forceinline__ unsigned mul2u(unsigned a, unsigned b) {
    return as_u(__hmul2(as_h(a), as_h(b)));
}

// m16n8k16 f16 MMA with f16 accumulators (C/D = 2 x f16x2 regs)
__device__ __forceinline__ void mma_f16(unsigned c[2],
                                        unsigned a0, unsigned a1, unsigned a2, unsigned a3,
                                        unsigned b0, unsigned b1) {
    asm("mma.sync.aligned.m16n8k16.row.col.f16.f16.f16.f16 "
        "{%0,%1},{%2,%3,%4,%5},{%6,%7},{%0,%1};"
        : "+r"(c[0]), "+r"(c[1])
        : "r"(a0), "r"(a1), "r"(a2), "r"(a3), "r"(b0), "r"(b1));
}

__global__ __launch_bounds__(WARPS_PER_CTA * 32, 3)
void aero_kernel(const float* __restrict__ v, const float* __restrict__ w,
                 const float* __restrict__ W1, const float* __restrict__ b1,
                 const float* __restrict__ W2, const float* __restrict__ b2,
                 const float* __restrict__ Wd1, const float* __restrict__ bd1,
                 const float* __restrict__ Wd2, const float* __restrict__ bd2,
                 const float* __restrict__ bias,
                 float* __restrict__ out, int n)
{
    __shared__ float sfeat[WARPS_PER_CTA][32][3];
    __shared__ float sy[WARPS_PER_CTA][32][3];
    __shared__ float sframe[WARPS_PER_CTA][32][6];
    __shared__ float sbias[3];
    // weight fragments (f16x2 words, lane-indexed, warp-invariant)
    __shared__ unsigned sB1[4 * 32];                 // nt*32+lane
    __shared__ unsigned sB2[2 * 4 * 2 * 32];         // ((ks*4+nt)*2+j)*32+lane
    __shared__ unsigned sB3[2 * 4 * 2 * 32];
    __shared__ unsigned sB4[2 * 2 * 32];             // (ks*2+j)*32+lane
    // packed f16x2 bias pairs
    __shared__ unsigned sb2p[16], sbd1p[16];         // nt*4 + (lane&3)
    __shared__ unsigned sbd2pp[4];                   // lane&3 (bd2 padded 3->8)

    const int lane = threadIdx.x & 31;
    const int warp = threadIdx.x >> 5;
    const long gwarp = (long)blockIdx.x * WARPS_PER_CTA + warp;
    const int tid = threadIdx.x;

    // ---- packed bias tables ----
    if (tid < 16) {
        const int nt = tid >> 2, q = (tid & 3) * 2;
        sb2p[tid]  = pack_h2(b2[8 * nt + q],  b2[8 * nt + q + 1]);
    } else if (tid < 32) {
        const int r = tid - 16;
        const int nt = r >> 2, q = (r & 3) * 2;
        sbd1p[r] = pack_h2(bd1[8 * nt + q], bd1[8 * nt + q + 1]);
    } else if (tid < 36) {
        const int q = (tid - 32) * 2;
        sbd2pp[tid - 32] = pack_h2(q < 3 ? bd2[q] : 0.0f, q + 1 < 3 ? bd2[q + 1] : 0.0f);
    } else if (tid < 39) {
        sbias[tid - 36] = bias[tid - 36];
    }

    // ---- weight fragment tables ----
    for (int idx = tid; idx < 2 * 4 * 2 * 32; idx += WARPS_PER_CTA * 32) {
        const int ln   = idx & 31;
        const int rest = idx >> 5;
        const int j    = rest & 1;
        const int nt   = (rest >> 1) & 3;
        const int ks   = rest >> 3;
        const int jrow = 8 * nt + (ln >> 2);
        const int k0   = 16 * ks + (ln & 3) * 2 + (j ? 8 : 0);
        sB2[idx] = pack_h2(W2[jrow * HID + k0],  W2[jrow * HID + k0 + 1]);
        sB3[idx] = pack_h2(Wd1[jrow * HID + k0], Wd1[jrow * HID + k0 + 1]);
    }
    // layer 1: K padded 3->16, k=3 slot carries b1 (A supplies 1.0 there)
    for (int idx = tid; idx < 4 * 32; idx += WARPS_PER_CTA * 32) {
        const int ln = idx & 31;
        const int nt = idx >> 5;
        const int j  = 8 * nt + (ln >> 2);
        const int kb = (ln & 3) * 2;
        float x = 0.0f, y = 0.0f;
        if (kb == 0)      { x = W1[j * 3 + 0]; y = W1[j * 3 + 1]; }
        else if (kb == 2) { x = W1[j * 3 + 2]; y = b1[j]; }
        sB1[idx] = pack_h2(x, y);
    }
    // layer 4: n padded 3->8
    for (int idx = tid; idx < 2 * 2 * 32; idx += WARPS_PER_CTA * 32) {
        const int ln = idx & 31;
        const int rest = idx >> 5;
        const int j  = rest & 1;
        const int ks = rest >> 1;
        const int jr = ln >> 2;
        const int k0 = 16 * ks + (ln & 3) * 2 + (j ? 8 : 0);
        sB4[idx] = pack_h2(jr < 3 ? Wd2[jr * HID + k0] : 0.0f,
                           jr < 3 ? Wd2[jr * HID + k0 + 1] : 0.0f);
    }
    __syncthreads();

    const int qq = lane & 3;
    const __half2 sl2 = __float2half2_rn(SLOPE);

    // ---- prefetch tile 0 inputs ----
    float cvx = 0, cvy = 0, cvz = 0, cwx = 0, cwy = 0, cwz = 0;
    {
        const long row0 = gwarp * TILES_PER_WARP * 32 + lane;
        if (row0 < n) {
            cvx = v[row0 * 3 + 0]; cvy = v[row0 * 3 + 1]; cvz = v[row0 * 3 + 2];
            cwx = w[row0 * 3 + 0]; cwy = w[row0 * 3 + 1]; cwz = w[row0 * 3 + 2];
        }
    }

    // ============================ main tile loop ============================
    for (int t = 0; t < TILES_PER_WARP; t++) {
        const long rowbase = (gwarp * TILES_PER_WARP + t) * 32;
        if (rowbase >= n) break;
        const long row = rowbase + lane;
        const bool ok = row < n;

        // ---- Gram-Schmidt from prefetched regs; frame + feat to smem ----
        {
            const float sv = fmaf(cvx, cvx, fmaf(cvy, cvy, cvz * cvz));
            const float iv = rsqrtf(fmaxf(sv, 1e-35f));
            const float v0 = cvx * iv, v1 = cvy * iv, v2 = cvz * iv;
            const float d  = fmaf(cwx, v0, fmaf(cwy, v1, cwz * v2));
            const float ox = fmaf(-d, v0, cwx);
            const float oy = fmaf(-d, v1, cwy);
            const float oz = fmaf(-d, v2, cwz);
            const float sw = fmaf(ox, ox, fmaf(oy, oy, oz * oz));
            const float iw = rsqrtf(fmaxf(sw, 1e-35f));
            const float w0 = ox * iw, w1 = oy * iw, w2 = oz * iw;

            sframe[warp][lane][0] = v0; sframe[warp][lane][1] = v1; sframe[warp][lane][2] = v2;
            sframe[warp][lane][3] = w0; sframe[warp][lane][4] = w1; sframe[warp][lane][5] = w2;
            sfeat[warp][lane][0] = fmaf(cvx, v0, fmaf(cvy, v1, cvz * v2));
            sfeat[warp][lane][1] = d;
            sfeat[warp][lane][2] = fmaf(cwx, w0, fmaf(cwy, w1, cwz * w2));
        }
        __syncwarp();

        // ---- prefetch next tile's inputs (hidden behind MMA chain) ----
        if (t + 1 < TILES_PER_WARP) {
            const long nrow = rowbase + 32 + lane;
            cvx = cvy = cvz = cwx = cwy = cwz = 0.0f;
            if (nrow < n) {
                cvx = v[nrow * 3 + 0]; cvy = v[nrow * 3 + 1]; cvz = v[nrow * 3 + 2];
                cwx = w[nrow * 3 + 0]; cwy = w[nrow * 3 + 1]; cwz = w[nrow * 3 + 2];
            }
        }

        // ---- layer 1, both 16-row tiles ----
        unsigned h1p[2][4][2];
        {
            unsigned a0[2], a1[2];
            #pragma unroll
            for (int mt = 0; mt < 2; mt++) {
                const int r1 = mt * 16 + (lane >> 2);
                const int r2 = r1 + 8;
                unsigned x0 = 0, x1 = 0;
                if (qq == 0) {
                    x0 = pack_h2(sfeat[warp][r1][0], sfeat[warp][r1][1]);
                    x1 = pack_h2(sfeat[warp][r2][0], sfeat[warp][r2][1]);
                } else if (qq == 1) {
                    x0 = pack_h2(sfeat[warp][r1][2], 1.0f);   // k=3 lane -> +b1
                    x1 = pack_h2(sfeat[warp][r2][2], 1.0f);
                }
                a0[mt] = x0; a1[mt] = x1;
            }
            #pragma unroll
            for (int mt = 0; mt < 2; mt++)
                #pragma unroll
                for (int nt = 0; nt < 4; nt++) {
                    unsigned C[2] = {0u, 0u};
                    mma_f16(C, a0[mt], a1[mt], 0u, 0u, sB1[nt * 32 + lane], 0u);
                    h1p[mt][nt][0] = lrelu2(C[0], sl2);
                    h1p[mt][nt][1] = lrelu2(C[1], sl2);
                }
        }

        // ---- layer 2: h = lrelu(h1 @ W2^T + b2) * h1 ----
        unsigned A2[2][4][2];
        #pragma unroll
        for (int mt = 0; mt < 2; mt++)
            #pragma unroll
            for (int nt = 0; nt < 4; nt++) {
                const unsigned bb = sb2p[nt * 4 + qq];
                unsigned C[2] = {bb, bb};
                mma_f16(C, h1p[mt][0][0], h1p[mt][0][1], h1p[mt][1][0], h1p[mt][1][1],
                        sB2[(nt * 2 + 0) * 32 + lane], sB2[(nt * 2 + 1) * 32 + lane]);
                mma_f16(C, h1p[mt][2][0], h1p[mt][2][1], h1p[mt][3][0], h1p[mt][3][1],
                        sB2[((4 + nt) * 2 + 0) * 32 + lane], sB2[((4 + nt) * 2 + 1) * 32 + lane]);
                A2[mt][nt][0] = mul2u(lrelu2(C[0], sl2), h1p[mt][nt][0]);
                A2[mt][nt][1] = mul2u(lrelu2(C[1], sl2), h1p[mt][nt][1]);
            }

        // ---- layer 3: g = lrelu(h @ Wd1^T + bd1) ----
        unsigned A3[2][4][2];
        #pragma unroll
        for (int mt = 0; mt < 2; mt++)
            #pragma unroll
            for (int nt = 0; nt < 4; nt++) {
                const unsigned bb = sbd1p[nt * 4 + qq];
                unsigned C[2] = {bb, bb};
                mma_f16(C, A2[mt][0][0], A2[mt][0][1], A2[mt][1][0], A2[mt][1][1],
                        sB3[(nt * 2 + 0) * 32 + lane], sB3[(nt * 2 + 1) * 32 + lane]);
                mma_f16(C, A2[mt][2][0], A2[mt][2][1], A2[mt][3][0], A2[mt][3][1],
                        sB3[((4 + nt) * 2 + 0) * 32 + lane], sB3[((4 + nt) * 2 + 1) * 32 + lane]);
                A3[mt][nt][0] = lrelu2(C[0], sl2);
                A3[mt][nt][1] = lrelu2(C[1], sl2);
            }

        // ---- layer 4 + y scatter ----
        #pragma unroll
        for (int mt = 0; mt < 2; mt++) {
            const unsigned b4 = sbd2pp[qq];
            unsigned C4[2] = {b4, b4};
            mma_f16(C4, A3[mt][0][0], A3[mt][0][1], A3[mt][1][0], A3[mt][1][1],
                    sB4[(0 * 2 + 0) * 32 + lane], sB4[(0 * 2 + 1) * 32 + lane]);
            mma_f16(C4, A3[mt][2][0], A3[mt][2][1], A3[mt][3][0], A3[mt][3][1],
                    sB4[(1 * 2 + 0) * 32 + lane], sB4[(1 * 2 + 1) * 32 + lane]);
            const int r1 = mt * 16 + (lane >> 2);
            const int r2 = r1 + 8;
            const float2 f0 = __half22float2(as_h(C4[0]));   // row r1: cols cc, cc+1
            const float2 f1 = __half22float2(as_h(C4[1]));   // row r2
            if (qq == 0) {
                sy[warp][r1][0] = f0.x; sy[warp][r1][1] = f0.y;
                sy[warp][r2][0] = f1.x; sy[warp][r2][1] = f1.y;
            } else if (qq == 1) {
                sy[warp][r1][2] = f0.x;
                sy[warp][r2][2] = f1.x;
            }
        }
        __syncwarp();

        // ---- epilogue: reload frame, recompute u = v_on x w_on, rotate ----
        if (ok) {
            const float v0 = sframe[warp][lane][0], v1 = sframe[warp][lane][1], v2 = sframe[warp][lane][2];
            const float w0 = sframe[warp][lane][3], w1 = sframe[warp][lane][4], w2 = sframe[warp][lane][5];
            const float u0 = fmaf(v1, w2, -v2 * w1);
            const float u1 = fmaf(v2, w0, -v0 * w2);
            const float u2 = fmaf(v0, w1, -v1 * w0);
            const float y0 = sy[warp][lane][0];
            const float y1 = sy[warp][lane][1];
            const float y2 = sy[warp][lane][2];
            out[row * 3 + 0] = fmaf(v0, y0, fmaf(w0, y1, fmaf(u0, y2, sbias[0])));
            out[row * 3 + 1] = fmaf(v1, y0, fmaf(w1, y1, fmaf(u1, y2, sbias[1])));
            out[row * 3 + 2] = fmaf(v2, y0, fmaf(w2, y1, fmaf(u2, y2, sbias[2])));
        }
        __syncwarp();
    }
}

extern "C" void kernel_launch(void* const* d_in, const int* in_sizes, int n_in,
                              void* d_out, int out_size)
{
    const float* v    = (const float*)d_in[0];
    const float* w    = (const float*)d_in[1];
    const float* W1   = (const float*)d_in[2];
    const float* b1   = (const float*)d_in[3];
    const float* W2   = (const float*)d_in[4];
    const float* b2   = (const float*)d_in[5];
    const float* Wd1  = (const float*)d_in[6];
    const float* bd1  = (const float*)d_in[7];
    const float* Wd2  = (const float*)d_in[8];
    const float* bd2  = (const float*)d_in[9];
    const float* bias = (const float*)d_in[10];
    float* out = (float*)d_out;

    const int n = in_sizes[0] / 3;
    const long tiles = ((long)n + 31) / 32;
    const long warps = (tiles + TILES_PER_WARP - 1) / TILES_PER_WARP;
    const int blocks = (int)((warps + WARPS_PER_CTA - 1) / WARPS_PER_CTA);
    aero_kernel<<<blocks, WARPS_PER_CTA * 32>>>(v, w, W1, b1, W2, b2, Wd1, bd1,
                                               Wd2, bd2, bias, out, n);
}